// round 14
// baseline (speedup 1.0000x reference)
#include <cuda_runtime.h>
#include <math.h>

#define Bq 8
#define Nn 768
#define Tt 769
#define Dd 256
#define Hh 8
#define Ll 6
#define Ff 128
#define Mrows (Bq*Tt)   // 6152
#define LDD (Ll*Dd*Dd)

__device__ float g_bias[Bq*Tt*Tt];
__device__ float g_x  [Mrows*Dd];
__device__ float g_xn [Mrows*Dd];
__device__ float g_q  [Mrows*Dd];
__device__ float g_k  [Mrows*Dd];
__device__ float g_v  [Mrows*Dd];
__device__ float g_att[Mrows*Dd];
__device__ float g_m1 [Mrows*Dd];
__device__ float g_deg[Bq*Nn];
__device__ float g_degmax[Bq];
__device__ float g_wr [6*LDD];     // tf32-pre-rounded weights: q,k,v,o,fc1,fc2

// ---------------------------------------------------------------------------
__device__ __forceinline__ unsigned f2tf(float x) {
    unsigned u; asm("cvt.rna.tf32.f32 %0, %1;" : "=r"(u) : "f"(x)); return u;
}
__device__ __forceinline__ float roundtf(float x) {
    return __uint_as_float(f2tf(x));
}
__device__ __forceinline__ void mma_tf32(float* d,
                                         unsigned a0, unsigned a1, unsigned a2, unsigned a3,
                                         unsigned b0, unsigned b1) {
    asm volatile("mma.sync.aligned.m16n8k8.row.col.f32.tf32.tf32.f32 "
                 "{%0,%1,%2,%3}, {%4,%5,%6,%7}, {%8,%9}, {%0,%1,%2,%3};\n"
                 : "+f"(d[0]), "+f"(d[1]), "+f"(d[2]), "+f"(d[3])
                 : "r"(a0), "r"(a1), "r"(a2), "r"(a3), "r"(b0), "r"(b1));
}
__device__ __forceinline__ void cpa16(float* dst, const float* src, bool pred) {
    unsigned d = (unsigned)__cvta_generic_to_shared(dst);
    int sz = pred ? 16 : 0;
    asm volatile("cp.async.ca.shared.global [%0], [%1], 16, %2;\n"
                 :: "r"(d), "l"(src), "r"(sz));
}
#define CP_COMMIT() asm volatile("cp.async.commit_group;\n")
#define CP_WAIT1()  asm volatile("cp.async.wait_group 1;\n")
#define CP_WAIT0()  asm volatile("cp.async.wait_group 0;\n")

// ---------------------------------------------------------------------------
__global__ void roundw_kernel(const float* __restrict__ qw, const float* __restrict__ kw,
                              const float* __restrict__ vw, const float* __restrict__ ow,
                              const float* __restrict__ f1, const float* __restrict__ f2) {
    int idx = blockIdx.x * 256 + threadIdx.x;
    int sel = idx / LDD, off = idx % LDD;
    const float* src = (sel == 0) ? qw : (sel == 1) ? kw : (sel == 2) ? vw :
                       (sel == 3) ? ow : (sel == 4) ? f1 : f2;
    g_wr[idx] = roundtf(src[off]);
}

// ---------------------------------------------------------------------------
__global__ void deg_kernel(const int* __restrict__ adj) {
    int row  = blockIdx.x * 8 + (threadIdx.x >> 5);
    int lane = threadIdx.x & 31;
    const int* a = adj + (size_t)row * Nn;
    float s = 0.f;
    #pragma unroll
    for (int k2 = 0; k2 < Nn / 32; k2++) s += (float)a[lane + 32 * k2];
    #pragma unroll
    for (int o = 16; o; o >>= 1) s += __shfl_xor_sync(0xffffffffu, s, o);
    if (lane == 0) g_deg[row] = s;
}

__global__ void degmax_kernel() {
    int b = blockIdx.x, tid = threadIdx.x;
    float m = 0.f;
    for (int i = tid; i < Nn; i += 256) m = fmaxf(m, g_deg[b * Nn + i]);
    __shared__ float sm[256];
    sm[tid] = m; __syncthreads();
    for (int s = 128; s; s >>= 1) {
        if (tid < s) sm[tid] = fmaxf(sm[tid], sm[tid + s]);
        __syncthreads();
    }
    if (tid == 0) g_degmax[b] = sm[0];
}

__global__ void bias_edge_kernel(const int* __restrict__ adj,
                                 const float* __restrict__ dist,
                                 const float* __restrict__ eoh,
                                 const float* __restrict__ etw,
                                 const float* __restrict__ noedge,
                                 const float* __restrict__ degscale,
                                 const float* __restrict__ gamma) {
    int i = blockIdx.x, b = blockIdx.y;
    float e0 = etw[0], e1 = etw[1], e2 = etw[2], e3 = etw[3];
    float ne = noedge[0], ds = degscale[0], ga = gamma[0];
    float di = g_deg[b * Nn + i];
    float inv_dmx = 1.f / (g_degmax[b] + 1e-6f);
    size_t base = ((size_t)b * Nn + i) * Nn;
    #pragma unroll
    for (int jj = 0; jj < Nn / 256; jj++) {
        int j = threadIdx.x + jj * 256;
        const float* eo = eoh + (base + j) * 4;
        float e = eo[0] * e0 + eo[1] * e1 + eo[2] * e2 + eo[3] * e3 - ga * dist[base + j];
        if (adj[base + j] == 0) e += ne;
        e += ds * (di + g_deg[b * Nn + j]) * inv_dmx;
        g_bias[(size_t)b * Tt * Tt + (size_t)(i + 1) * Tt + (j + 1)] = e;
    }
}

__global__ void bias_fill_kernel(const float* v2n, const float* n2v, const float* vself) {
    int b = blockIdx.x, part = blockIdx.y;
    float a = v2n[0], c = n2v[0];
    size_t base = (size_t)b * Tt * Tt;
    int t0 = 1 + part * 192;
    for (int t = t0 + threadIdx.x; t < t0 + 192 && t < Tt; t += 256) {
        g_bias[base + t]              = a;
        g_bias[base + (size_t)t * Tt] = c;
    }
    if (part == 0 && threadIdx.x == 0) g_bias[base] = vself[0];
}

// ---------------------------------------------------------------------------
__global__ void proj_kernel(const float* __restrict__ nf, const float* __restrict__ W,
                            const float* __restrict__ bb, const float* __restrict__ cls) {
    int t = blockIdx.x, b = blockIdx.y, tid = threadIdx.x;
    if (t == 0) { g_x[((size_t)b * Tt) * Dd + tid] = cls[tid]; return; }
    __shared__ float sm[Ff];
    if (tid < Ff) sm[tid] = nf[((size_t)b * Nn + (t - 1)) * Ff + tid];
    __syncthreads();
    float a = bb[tid];
    #pragma unroll 8
    for (int k2 = 0; k2 < Ff; k2++) a = fmaf(sm[k2], W[k2 * Dd + tid], a);
    g_x[((size_t)b * Tt + t) * Dd + tid] = a;
}

// ---------------------------------------------------------------------------
__global__ void ln_kernel(const float* __restrict__ x, const float* __restrict__ g,
                          const float* __restrict__ bb, float* __restrict__ xn) {
    int row  = blockIdx.x * 8 + (threadIdx.x >> 5);
    int lane = threadIdx.x & 31;
    const float* xr = x + (size_t)row * Dd;
    float v[8], s = 0.f, s2 = 0.f;
    #pragma unroll
    for (int k2 = 0; k2 < 8; k2++) {
        v[k2] = xr[lane + 32 * k2];
        s += v[k2]; s2 += v[k2] * v[k2];
    }
    #pragma unroll
    for (int o = 16; o; o >>= 1) {
        s  += __shfl_xor_sync(0xffffffffu, s, o);
        s2 += __shfl_xor_sync(0xffffffffu, s2, o);
    }
    float mean = s * (1.f / Dd);
    float var  = s2 * (1.f / Dd) - mean * mean;
    float rs = rsqrtf(var + 1e-5f);
    float* orow = xn + (size_t)row * Dd;
    #pragma unroll
    for (int k2 = 0; k2 < 8; k2++) {
        int d = lane + 32 * k2;
        orow[d] = roundtf((v[k2] - mean) * rs * g[d] + bb[d]);
    }
}

// ---------------------------------------------------------------------------
// shared epilogue helper
template<int EPI>
__device__ __forceinline__ void epi_store(float* cp, const float* rp, float v0, float v1) {
    if (EPI == 0) { v0 = roundtf(v0); v1 = roundtf(v1); }
    if (EPI == 1) {
        v0 = roundtf(0.5f * v0 * (1.f + erff(v0 * 0.70710678118654752f)));
        v1 = roundtf(0.5f * v1 * (1.f + erff(v1 * 0.70710678118654752f)));
    }
    if (EPI == 2) { v0 += rp[0]; v1 += rp[1]; }
    *(float2*)cp = make_float2(v0, v1);
}

// ---------------------------------------------------------------------------
// GEMM body A: BM=128 BN=128 BK=32, 8 warps (4x2, warp 32x64), double-buffered.
// Used by gemm_qkv (294 blocks — good packing).
#define GA_STRIDE 36
#define GW_STRIDE 136
#define GEMM_SMEM   ((2*128*GA_STRIDE + 2*32*GW_STRIDE) * 4)   // 71.7 KB
#define GEMM64_SMEM ((2*64*GA_STRIDE  + 2*32*GW_STRIDE) * 4)   // 53.2 KB

template<int EPI>
__device__ __forceinline__ void gemm_body128(float* sm,
                                             const float* __restrict__ A,
                                             const float* __restrict__ W,
                                             const float* __restrict__ bias,
                                             const float* __restrict__ Cres,
                                             float* __restrict__ Cout,
                                             int m0, int n0) {
    const int M = Mrows;
    float* As = sm;                         // [2][128][36]
    float* Ws = sm + 2 * 128 * GA_STRIDE;   // [2][32][136]
    int tid = threadIdx.x, w = tid >> 5, lane = tid & 31;
    int g = lane >> 2, t = lane & 3;
    int wm = (w >> 1) * 32, wn = (w & 1) * 64;

    auto issue = [&](int kt, int buf) {
        int k0 = kt * 32;
        float* Ab = As + buf * 128 * GA_STRIDE;
        #pragma unroll
        for (int r = 0; r < 4; r++) {
            int idx = tid + 256 * r;
            int m = idx >> 3, ch = idx & 7;
            bool p = (m0 + m) < M;
            const float* src = A + (size_t)(p ? (m0 + m) : 0) * 256 + k0 + ch * 4;
            cpa16(Ab + m * GA_STRIDE + ch * 4, src, p);
        }
        float* Wb = Ws + buf * 32 * GW_STRIDE;
        #pragma unroll
        for (int r = 0; r < 4; r++) {
            int idx = tid + 256 * r;
            int kk = idx >> 5, ch = idx & 31;
            cpa16(Wb + kk * GW_STRIDE + ch * 4, W + (size_t)(k0 + kk) * 256 + n0 + ch * 4, true);
        }
        CP_COMMIT();
    };

    float acc[2][8][4];
    #pragma unroll
    for (int i = 0; i < 2; i++)
        #pragma unroll
        for (int j = 0; j < 8; j++)
            #pragma unroll
            for (int c = 0; c < 4; c++) acc[i][j][c] = 0.f;

    issue(0, 0);
    for (int kt = 0; kt < 8; kt++) {
        int buf = kt & 1;
        if (kt < 7) { issue(kt + 1, buf ^ 1); CP_WAIT1(); }
        else        { CP_WAIT0(); }
        __syncthreads();
        const unsigned* Ab = (const unsigned*)(As + buf * 128 * GA_STRIDE);
        const unsigned* Wb = (const unsigned*)(Ws + buf * 32 * GW_STRIDE);
        #pragma unroll
        for (int ks = 0; ks < 4; ks++) {
            int kb = ks * 8;
            unsigned a[2][4];
            #pragma unroll
            for (int mf = 0; mf < 2; mf++) {
                int mb = wm + mf * 16;
                a[mf][0] = Ab[(mb + g)     * GA_STRIDE + kb + t];
                a[mf][1] = Ab[(mb + g + 8) * GA_STRIDE + kb + t];
                a[mf][2] = Ab[(mb + g)     * GA_STRIDE + kb + t + 4];
                a[mf][3] = Ab[(mb + g + 8) * GA_STRIDE + kb + t + 4];
            }
            #pragma unroll
            for (int nf = 0; nf < 8; nf++) {
                unsigned b0 = Wb[(kb + t)     * GW_STRIDE + wn + nf * 8 + g];
                unsigned b1 = Wb[(kb + t + 4) * GW_STRIDE + wn + nf * 8 + g];
                #pragma unroll
                for (int mf = 0; mf < 2; mf++)
                    mma_tf32(acc[mf][nf], a[mf][0], a[mf][1], a[mf][2], a[mf][3], b0, b1);
            }
        }
        __syncthreads();
    }
    #pragma unroll
    for (int mf = 0; mf < 2; mf++) {
        int row0 = m0 + wm + mf * 16 + g;
        #pragma unroll
        for (int nf = 0; nf < 8; nf++) {
            int col = n0 + wn + nf * 8 + 2 * t;
            float bv0 = bias[col], bv1 = bias[col + 1];
            #pragma unroll
            for (int half = 0; half < 2; half++) {
                int row = row0 + half * 8;
                if (row >= M) continue;
                epi_store<EPI>(Cout + (size_t)row * 256 + col,
                               Cres + (size_t)row * 256 + col,
                               acc[mf][nf][half * 2 + 0] + bv0,
                               acc[mf][nf][half * 2 + 1] + bv1);
            }
        }
    }
}

// GEMM body B: BM=64 BN=128 BK=32, 8 warps (2x4, warp 32x32), double-buffered.
// Used by gemm_one (194 blocks vs 98 -> 2x SM coverage). NO 3-block reg cap.
template<int EPI>
__device__ __forceinline__ void gemm_body64(float* sm,
                                            const float* __restrict__ A,
                                            const float* __restrict__ W,
                                            const float* __restrict__ bias,
                                            const float* __restrict__ Cres,
                                            float* __restrict__ Cout,
                                            int m0, int n0) {
    const int M = Mrows;
    float* As = sm;                        // [2][64][36]
    float* Ws = sm + 2 * 64 * GA_STRIDE;   // [2][32][136]
    int tid = threadIdx.x, w = tid >> 5, lane = tid & 31;
    int g = lane >> 2, t = lane & 3;
    int wm = (w >> 2) * 32, wn = (w & 3) * 32;

    auto issue = [&](int kt, int buf) {
        int k0 = kt * 32;
        float* Ab = As + buf * 64 * GA_STRIDE;
        #pragma unroll
        for (int r = 0; r < 2; r++) {
            int idx = tid + 256 * r;
            int m = idx >> 3, ch = idx & 7;
            bool p = (m0 + m) < M;
            const float* src = A + (size_t)(p ? (m0 + m) : 0) * 256 + k0 + ch * 4;
            cpa16(Ab + m * GA_STRIDE + ch * 4, src, p);
        }
        float* Wb = Ws + buf * 32 * GW_STRIDE;
        #pragma unroll
        for (int r = 0; r < 4; r++) {
            int idx = tid + 256 * r;
            int kk = idx >> 5, ch = idx & 31;
            cpa16(Wb + kk * GW_STRIDE + ch * 4, W + (size_t)(k0 + kk) * 256 + n0 + ch * 4, true);
        }
        CP_COMMIT();
    };

    float acc[2][4][4];
    #pragma unroll
    for (int i = 0; i < 2; i++)
        #pragma unroll
        for (int j = 0; j < 4; j++)
            #pragma unroll
            for (int c = 0; c < 4; c++) acc[i][j][c] = 0.f;

    issue(0, 0);
    for (int kt = 0; kt < 8; kt++) {
        int buf = kt & 1;
        if (kt < 7) { issue(kt + 1, buf ^ 1); CP_WAIT1(); }
        else        { CP_WAIT0(); }
        __syncthreads();
        const unsigned* Ab = (const unsigned*)(As + buf * 64 * GA_STRIDE);
        const unsigned* Wb = (const unsigned*)(Ws + buf * 32 * GW_STRIDE);
        #pragma unroll
        for (int ks = 0; ks < 4; ks++) {
            int kb = ks * 8;
            unsigned a[2][4];
            #pragma unroll
            for (int mf = 0; mf < 2; mf++) {
                int mb = wm + mf * 16;
                a[mf][0] = Ab[(mb + g)     * GA_STRIDE + kb + t];
                a[mf][1] = Ab[(mb + g + 8) * GA_STRIDE + kb + t];
                a[mf][2] = Ab[(mb + g)     * GA_STRIDE + kb + t + 4];
                a[mf][3] = Ab[(mb + g + 8) * GA_STRIDE + kb + t + 4];
            }
            #pragma unroll
            for (int nf = 0; nf < 4; nf++) {
                unsigned b0 = Wb[(kb + t)     * GW_STRIDE + wn + nf * 8 + g];
                unsigned b1 = Wb[(kb + t + 4) * GW_STRIDE + wn + nf * 8 + g];
                #pragma unroll
                for (int mf = 0; mf < 2; mf++)
                    mma_tf32(acc[mf][nf], a[mf][0], a[mf][1], a[mf][2], a[mf][3], b0, b1);
            }
        }
        __syncthreads();
    }
    #pragma unroll
    for (int mf = 0; mf < 2; mf++) {
        int row0 = m0 + wm + mf * 16 + g;
        #pragma unroll
        for (int nf = 0; nf < 4; nf++) {
            int col = n0 + wn + nf * 8 + 2 * t;
            float bv0 = bias[col], bv1 = bias[col + 1];
            #pragma unroll
            for (int half = 0; half < 2; half++) {
                int row = row0 + half * 8;
                if (row >= M) continue;
                epi_store<EPI>(Cout + (size_t)row * 256 + col,
                               Cres + (size_t)row * 256 + col,
                               acc[mf][nf][half * 2 + 0] + bv0,
                               acc[mf][nf][half * 2 + 1] + bv1);
            }
        }
    }
}

template<int EPI>
__global__ void __launch_bounds__(256, 2)
gemm_one(const float* __restrict__ A, const float* __restrict__ W,
         const float* __restrict__ bias, const float* __restrict__ Cres,
         float* __restrict__ Cout) {
    extern __shared__ float sm[];
    gemm_body64<EPI>(sm, A, W, bias, Cres, Cout, blockIdx.y * 64, blockIdx.x * 128);
}

__global__ void __launch_bounds__(256, 2)
gemm_qkv(const float* __restrict__ A, const float* __restrict__ Wr,
         const float* bb0, float* c0,
         const float* bb1, float* c1,
         const float* bb2, float* c2) {
    extern __shared__ float sm[];
    int sel = blockIdx.x >> 1;
    int n0 = (blockIdx.x & 1) * 128, m0 = blockIdx.y * 128;
    const float* W  = Wr + (size_t)sel * LDD;
    const float* bb = (sel == 0) ? bb0 : (sel == 1) ? bb1 : bb2;
    float*       C  = (sel == 0) ? c0  : (sel == 1) ? c1  : c2;
    gemm_body128<0>(sm, A, W, bb, C, C, m0, n0);
}

// ---------------------------------------------------------------------------
// Flash attention (R11 config, unchanged): 256 thr / 8 warps, 128 q rows/block,
// double-buffered K/V, interior-tile bias fast path, act-guard.
#define AQ_STRIDE 36
#define AK_STRIDE 36
#define AV_STRIDE 40
#define AP_STRIDE 68
#define ATTN_SMEM ((128*AQ_STRIDE + 2*64*AK_STRIDE + 2*64*AV_STRIDE + 8*16*AP_STRIDE) * 4)

__global__ void __launch_bounds__(256, 2)
attn_tc(const float* __restrict__ q, const float* __restrict__ k,
        const float* __restrict__ v, const float* __restrict__ bias,
        float* __restrict__ out) {
    extern __shared__ float sm[];
    unsigned* Qs = (unsigned*)sm;                         // [128][36]
    float*    Ks = sm + 128 * AQ_STRIDE;                  // [2][64][36]
    float*    Vs = Ks + 2 * 64 * AK_STRIDE;               // [2][64][40]
    unsigned* Ps = (unsigned*)(Vs + 2 * 64 * AV_STRIDE);  // [8][16][68]

    int b = blockIdx.x >> 3, h = blockIdx.x & 7;
    int q0 = blockIdx.y * 128;
    int tid = threadIdx.x, w = tid >> 5, lane = tid & 31;
    int g = lane >> 2, t = lane & 3;

    const float scale = 0.17677669529663687f;
    const float* kb_ = k + (size_t)b * Tt * Dd + h * 32;
    const float* vb_ = v + (size_t)b * Tt * Dd + h * 32;
    const float* biasb = bias + (size_t)b * Tt * Tt;

    auto issueKV = [&](int jt, int buf) {
        int j0 = jt * 64;
        float* Kb = Ks + buf * 64 * AK_STRIDE;
        float* Vb = Vs + buf * 64 * AV_STRIDE;
        #pragma unroll
        for (int r = 0; r < 2; r++) {
            int idx = tid + 256 * r;
            int key = idx >> 3, ch = idx & 7;
            int gj = j0 + key;
            bool p = gj < Tt;
            size_t off = (size_t)(p ? gj : 0) * 256 + ch * 4;
            cpa16(Kb + key * AK_STRIDE + ch * 4, kb_ + off, p);
            cpa16(Vb + key * AV_STRIDE + ch * 4, vb_ + off, p);
        }
        CP_COMMIT();
    };

    issueKV(0, 0);
    #pragma unroll
    for (int r = 0; r < 4; r++) {
        int idx = tid + 256 * r;
        int m = idx >> 3, k4 = (idx & 7) << 2;
        float4 qv = make_float4(0.f, 0.f, 0.f, 0.f);
        int qr = q0 + m;
        if (qr < Tt) qv = *(const float4*)(q + ((size_t)(b * Tt + qr)) * 256 + h * 32 + k4);
        Qs[m * AQ_STRIDE + k4 + 0] = f2tf(qv.x * scale);
        Qs[m * AQ_STRIDE + k4 + 1] = f2tf(qv.y * scale);
        Qs[m * AQ_STRIDE + k4 + 2] = f2tf(qv.z * scale);
        Qs[m * AQ_STRIDE + k4 + 3] = f2tf(qv.w * scale);
    }
    __syncthreads();
    int mb = w * 16;
    int r0g = q0 + mb + g, r1g = r0g + 8;
    bool act = (q0 + mb) < Tt;
    bool rowsok = r1g < Tt;

    unsigned qa[4][4];
    if (act) {
        #pragma unroll
        for (int ks = 0; ks < 4; ks++) {
            int kb2 = ks * 8;
            qa[ks][0] = Qs[(mb + g)     * AQ_STRIDE + kb2 + t];
            qa[ks][1] = Qs[(mb + g + 8) * AQ_STRIDE + kb2 + t];
            qa[ks][2] = Qs[(mb + g)     * AQ_STRIDE + kb2 + t + 4];
            qa[ks][3] = Qs[(mb + g + 8) * AQ_STRIDE + kb2 + t + 4];
        }
    }

    float mrow[2] = {-1e30f, -1e30f}, lrow[2] = {1.f, 1.f};
    float oacc[4][4];
    #pragma unroll
    for (int i = 0; i < 4; i++)
        #pragma unroll
        for (int c = 0; c < 4; c++) oacc[i][c] = 0.f;

    const int NTILES = (Tt + 63) / 64;  // 13

    for (int jt = 0; jt < NTILES; jt++) {
        int buf = jt & 1;
        int j0 = jt * 64;

        float s[8][4];
        if (act) {
            const float* br0 = biasb + (size_t)r0g * Tt + j0;
            const float* br1 = biasb + (size_t)r1g * Tt + j0;
            if (rowsok && jt < NTILES - 1) {
                #pragma unroll
                for (int nf = 0; nf < 8; nf++) {
                    int col = nf * 8 + 2 * t;
                    s[nf][0] = __ldg(br0 + col);
                    s[nf][1] = __ldg(br0 + col + 1);
                    s[nf][2] = __ldg(br1 + col);
                    s[nf][3] = __ldg(br1 + col + 1);
                }
            } else {
                #pragma unroll
                for (int nf = 0; nf < 8; nf++) {
                    int col = j0 + nf * 8 + 2 * t;
                    bool cok0 = col < Tt, cok1 = (col + 1) < Tt;
                    s[nf][0] = (r0g < Tt && cok0) ? __ldg(biasb + (size_t)r0g * Tt + col)     : -1e30f;
                    s[nf][1] = (r0g < Tt && cok1) ? __ldg(biasb + (size_t)r0g * Tt + col + 1) : -1e30f;
                    s[nf][2] = (rowsok && cok0)   ? __ldg(biasb + (size_t)r1g * Tt + col)     : -1e30f;
                    s[nf][3] = (rowsok && cok1)   ? __ldg(biasb + (size_t)r1g * Tt + col + 1) : -1e30f;
                }
            }
        }

        if (jt + 1 < NTILES) { issueKV(jt + 1, buf ^ 1); CP_WAIT1(); }
        else                 { CP_WAIT0(); }
        __syncthreads();

        if (act) {
            const unsigned* Kb = (const unsigned*)(Ks + buf * 64 * AK_STRIDE);
            const unsigned* Vb = (const unsigned*)(Vs + buf * 64 * AV_STRIDE);

            #pragma unroll
            for (int ks = 0; ks < 4; ks++) {
                int kb2 = ks * 8;
                #pragma unroll
                for (int nf = 0; nf < 8; nf++) {
                    unsigned b0 = Kb[(nf * 8 + g) * AK_STRIDE + kb2 + t];
                    unsigned b1 = Kb[(nf * 8 + g) * AK_STRIDE + kb2 + t + 4];
                    mma_tf32(s[nf], qa[ks][0], qa[ks][1], qa[ks][2], qa[ks][3], b0, b1);
                }
            }
            float tmax[2] = {-1e30f, -1e30f};
            #pragma unroll
            for (int nf = 0; nf < 8; nf++) {
                tmax[0] = fmaxf(tmax[0], fmaxf(s[nf][0], s[nf][1]));
                tmax[1] = fmaxf(tmax[1], fmaxf(s[nf][2], s[nf][3]));
            }
            #pragma unroll
            for (int o = 1; o <= 2; o <<= 1) {
                tmax[0] = fmaxf(tmax[0], __shfl_xor_sync(0xffffffffu, tmax[0], o));
                tmax[1] = fmaxf(tmax[1], __shfl_xor_sync(0xffffffffu, tmax[1], o));
            }
            float mn0 = fmaxf(mrow[0], tmax[0]), mn1 = fmaxf(mrow[1], tmax[1]);
            float corr0 = __expf(mrow[0] - mn0), corr1 = __expf(mrow[1] - mn1);
            bool first = (jt == 0);
            mrow[0] = mn0; mrow[1] = mn1;
            float sum0 = 0.f, sum1 = 0.f;
            #pragma unroll
            for (int nf = 0; nf < 8; nf++) {
                s[nf][0] = __expf(s[nf][0] - mn0); sum0 += s[nf][0];
                s[nf][1] = __expf(s[nf][1] - mn0); sum0 += s[nf][1];
                s[nf][2] = __expf(s[nf][2] - mn1); sum1 += s[nf][2];
                s[nf][3] = __expf(s[nf][3] - mn1); sum1 += s[nf][3];
            }
            #pragma unroll
            for (int o = 1; o <= 2; o <<= 1) {
                sum0 += __shfl_xor_sync(0xffffffffu, sum0, o);
                sum1 += __shfl_xor_sync(0xffffffffu, sum1, o);
            }
            lrow[0] = first ? sum0 : (lrow[0] * corr0 + sum0);
            lrow[1] = first ? sum1 : (lrow[1] * corr1 + sum1);
            #pragma unroll
            for (int i = 0; i < 4; i++) {
                oacc[i][0] *= corr0; oacc[i][1] *= corr0;
                oacc[i][2] *= corr1; oacc[i][3] *= corr1;
            }
            unsigned* Pw = Ps + w * 16 * AP_STRIDE;
            #pragma unroll
            for (int nf = 0; nf < 8; nf++) {
                int col = nf * 8 + 2 * t;
                Pw[g * AP_STRIDE + col]           = f2tf(s[nf][0]);
                Pw[g * AP_STRIDE + col + 1]       = f2tf(s[nf][1]);
                Pw[(g + 8) * AP_STRIDE + col]     = f2tf(s[nf][2]);
                Pw[(g + 8) * AP_STRIDE + col + 1] = f2tf(s[nf][3]);
            }
            __syncwarp();
            #pragma unroll
            for (int ks2 = 0; ks2 < 8; ks2++) {
                int kk = ks2 * 8;
                unsigned a0 = Pw[g * AP_STRIDE + kk + t];
                unsigned a1 = Pw[(g + 8) * AP_STRIDE + kk + t];
                unsigned a2 = Pw[g * AP_STRIDE + kk + t + 4];
                unsigned a3 = Pw[(g + 8) * AP_STRIDE + kk + t + 4];
                #pragma unroll
                for (int nf2 = 0; nf2 < 4; nf2++) {
                    unsigned b0 = Vb[(kk + t)     * AV_STRIDE + nf2 * 8 + g];
                    unsigned b1 = Vb[(kk + t + 4) * AV_STRIDE + nf2 * 8 + g];
                    mma_tf32(oacc[nf2], a0, a1, a2, a3, b0, b1);
                }
            }
        }
        __syncthreads();
    }
    if (act) {
        float inv0 = 1.f / lrow[0], inv1 = 1.f / lrow[1];
        #pragma unroll
        for (int nf2 = 0; nf2 < 4; nf2++) {
            int feat = nf2 * 8 + 2 * t;
            if (r0g < Tt)
                *(float2*)(out + ((size_t)(b * Tt + r0g)) * 256 + h * 32 + feat) =
                    make_float2(roundtf(oacc[nf2][0] * inv0), roundtf(oacc[nf2][1] * inv0));
            if (rowsok)
                *(float2*)(out + ((size_t)(b * Tt + r1g)) * 256 + h * 32 + feat) =
                    make_float2(roundtf(oacc[nf2][2] * inv1), roundtf(oacc[nf2][3] * inv1));
        }
    }
}

// ---------------------------------------------------------------------------
extern "C" void kernel_launch(void* const* d_in, const int* in_sizes, int n_in,
                              void* d_out, int out_size) {
    const float* nf       = (const float*)d_in[0];
    const int*   adj      = (const int*)  d_in[1];
    const float* dist     = (const float*)d_in[2];
    const float* eoh      = (const float*)d_in[3];
    const float* npw      = (const float*)d_in[4];
    const float* npb      = (const float*)d_in[5];
    const float* cls      = (const float*)d_in[6];
    const float* etw      = (const float*)d_in[7];
    const float* noedge   = (const float*)d_in[8];
    const float* degscale = (const float*)d_in[9];
    const float* gamma    = (const float*)d_in[10];
    const float* v2n      = (const float*)d_in[11];
    const float* n2v      = (const float*)d_in[12];
    const float* vself    = (const float*)d_in[13];
    const float* ln1g = (const float*)d_in[14]; const float* ln1b = (const float*)d_in[15];
    const float* qw   = (const float*)d_in[16]; const float* qb   = (const float*)d_in[17];
    const float* kw   = (const float*)d_in[18]; const float* kb   = (const float*)d_in[19];
    const float* vw   = (const float*)d_in[20]; const float* vb   = (const float*)d_in[21];
    const float* ow   = (const float*)d_in[22]; const float* ob   = (const float*)d_in[23];
    const float* ln2g = (const float*)d_in[24]; const float* ln2b = (const float*)d_in[25];
    const float* fc1w = (const float*)d_in[26]; const float* fc1b = (const float*)d_in[27];
    const float* fc2w = (const float*)d_in[28]; const float* fc2b = (const float*)d_in[29];

    float *p_x, *p_xn, *p_q, *p_k, *p_v, *p_att, *p_m1, *p_bias, *p_wr;
    cudaGetSymbolAddress((void**)&p_x,    g_x);
    cudaGetSymbolAddress((void**)&p_xn,   g_xn);
    cudaGetSymbolAddress((void**)&p_q,    g_q);
    cudaGetSymbolAddress((void**)&p_k,    g_k);
    cudaGetSymbolAddress((void**)&p_v,    g_v);
    cudaGetSymbolAddress((void**)&p_att,  g_att);
    cudaGetSymbolAddress((void**)&p_m1,   g_m1);
    cudaGetSymbolAddress((void**)&p_bias, g_bias);
    cudaGetSymbolAddress((void**)&p_wr,   g_wr);

    cudaFuncSetAttribute(gemm_qkv,    cudaFuncAttributeMaxDynamicSharedMemorySize, GEMM_SMEM);
    cudaFuncSetAttribute(gemm_one<1>, cudaFuncAttributeMaxDynamicSharedMemorySize, GEMM64_SMEM);
    cudaFuncSetAttribute(gemm_one<2>, cudaFuncAttributeMaxDynamicSharedMemorySize, GEMM64_SMEM);
    cudaFuncSetAttribute(attn_tc,     cudaFuncAttributeMaxDynamicSharedMemorySize, ATTN_SMEM);

    roundw_kernel<<<6 * LDD / 256, 256>>>(qw, kw, vw, ow, fc1w, fc2w);
    deg_kernel<<<(Bq * Nn) / 8, 256>>>(adj);
    degmax_kernel<<<Bq, 256>>>();
    bias_edge_kernel<<<dim3(Nn, Bq), 256>>>(adj, dist, eoh, etw, noedge, degscale, gamma);
    bias_fill_kernel<<<dim3(Bq, 4), 256>>>(v2n, n2v, vself);

    proj_kernel<<<dim3(Tt, Bq), 256>>>(nf, npw, npb, cls);

    dim3 ggrid (2, (Mrows + 63) / 64);      // (2, 97) = 194 blocks (BM=64)
    dim3 qgrid (6, (Mrows + 127) / 128);    // (6, 49) = 294 blocks (BM=128)
    dim3 agrid (Bq * Hh, (Tt + 127) / 128); // (64, 7) = 448 blocks
    for (int l = 0; l < Ll; l++) {
        size_t wo = (size_t)l * Dd * Dd;
        size_t bo = (size_t)l * Dd;
        bool last = (l == Ll - 1);
        ln_kernel<<<Mrows / 8, 256>>>(p_x, ln1g + bo, ln1b + bo, p_xn);
        gemm_qkv<<<qgrid, 256, GEMM_SMEM>>>(p_xn, p_wr + wo,
                                            qb + bo, p_q, kb + bo, p_k, vb + bo, p_v);
        attn_tc<<<agrid, 256, ATTN_SMEM>>>(p_q, p_k, p_v, p_bias, p_att);
        gemm_one<2><<<ggrid, 256, GEMM64_SMEM>>>(p_att, p_wr + 3 * LDD + wo, ob + bo, p_x, p_x);
        ln_kernel<<<Mrows / 8, 256>>>(p_x, ln2g + bo, ln2b + bo, p_xn);
        gemm_one<1><<<ggrid, 256, GEMM64_SMEM>>>(p_xn, p_wr + 4 * LDD + wo, fc1b + bo, p_m1, p_m1);
        gemm_one<2><<<ggrid, 256, GEMM64_SMEM>>>(p_m1, p_wr + 5 * LDD + wo, fc2b + bo,
                                                 p_x, last ? (float*)d_out : p_x);
    }
}

// round 15
// speedup vs baseline: 1.0230x; 1.0230x over previous
#include <cuda_runtime.h>
#include <math.h>

#define Bq 8
#define Nn 768
#define Tt 769
#define Dd 256
#define Hh 8
#define Ll 6
#define Ff 128
#define Mrows (Bq*Tt)   // 6152
#define LDD (Ll*Dd*Dd)
#define LOG2E 1.4426950408889634f

__device__ float g_bias[Bq*Tt*Tt];   // stored PRE-MULTIPLIED by log2(e)
__device__ float g_x  [Mrows*Dd];
__device__ float g_xn [Mrows*Dd];
__device__ float g_q  [Mrows*Dd];
__device__ float g_k  [Mrows*Dd];
__device__ float g_v  [Mrows*Dd];
__device__ float g_att[Mrows*Dd];
__device__ float g_m1 [Mrows*Dd];
__device__ float g_deg[Bq*Nn];
__device__ float g_degmax[Bq];
__device__ float g_wr [6*LDD];       // tf32-pre-rounded weights: q,k,v,o,fc1,fc2

// ---------------------------------------------------------------------------
__device__ __forceinline__ unsigned f2tf(float x) {
    unsigned u; asm("cvt.rna.tf32.f32 %0, %1;" : "=r"(u) : "f"(x)); return u;
}
__device__ __forceinline__ float roundtf(float x) {
    return __uint_as_float(f2tf(x));
}
__device__ __forceinline__ float ex2(float x) {   // bare EX2 (no pre-mul)
    float r; asm("ex2.approx.f32 %0, %1;" : "=f"(r) : "f"(x)); return r;
}
__device__ __forceinline__ void mma_tf32(float* d,
                                         unsigned a0, unsigned a1, unsigned a2, unsigned a3,
                                         unsigned b0, unsigned b1) {
    asm volatile("mma.sync.aligned.m16n8k8.row.col.f32.tf32.tf32.f32 "
                 "{%0,%1,%2,%3}, {%4,%5,%6,%7}, {%8,%9}, {%0,%1,%2,%3};\n"
                 : "+f"(d[0]), "+f"(d[1]), "+f"(d[2]), "+f"(d[3])
                 : "r"(a0), "r"(a1), "r"(a2), "r"(a3), "r"(b0), "r"(b1));
}
__device__ __forceinline__ void cpa16(float* dst, const float* src, bool pred) {
    unsigned d = (unsigned)__cvta_generic_to_shared(dst);
    int sz = pred ? 16 : 0;
    asm volatile("cp.async.ca.shared.global [%0], [%1], 16, %2;\n"
                 :: "r"(d), "l"(src), "r"(sz));
}
#define CP_COMMIT() asm volatile("cp.async.commit_group;\n")
#define CP_WAIT1()  asm volatile("cp.async.wait_group 1;\n")
#define CP_WAIT0()  asm volatile("cp.async.wait_group 0;\n")

// ---------------------------------------------------------------------------
__global__ void roundw_kernel(const float* __restrict__ qw, const float* __restrict__ kw,
                              const float* __restrict__ vw, const float* __restrict__ ow,
                              const float* __restrict__ f1, const float* __restrict__ f2) {
    int idx = blockIdx.x * 256 + threadIdx.x;
    int sel = idx / LDD, off = idx % LDD;
    const float* src = (sel == 0) ? qw : (sel == 1) ? kw : (sel == 2) ? vw :
                       (sel == 3) ? ow : (sel == 4) ? f1 : f2;
    g_wr[idx] = roundtf(src[off]);
}

// ---------------------------------------------------------------------------
__global__ void deg_kernel(const int* __restrict__ adj) {
    int row  = blockIdx.x * 8 + (threadIdx.x >> 5);
    int lane = threadIdx.x & 31;
    const int* a = adj + (size_t)row * Nn;
    float s = 0.f;
    #pragma unroll
    for (int k2 = 0; k2 < Nn / 32; k2++) s += (float)a[lane + 32 * k2];
    #pragma unroll
    for (int o = 16; o; o >>= 1) s += __shfl_xor_sync(0xffffffffu, s, o);
    if (lane == 0) g_deg[row] = s;
}

__global__ void degmax_kernel() {
    int b = blockIdx.x, tid = threadIdx.x;
    float m = 0.f;
    for (int i = tid; i < Nn; i += 256) m = fmaxf(m, g_deg[b * Nn + i]);
    __shared__ float sm[256];
    sm[tid] = m; __syncthreads();
    for (int s = 128; s; s >>= 1) {
        if (tid < s) sm[tid] = fmaxf(sm[tid], sm[tid + s]);
        __syncthreads();
    }
    if (tid == 0) g_degmax[b] = sm[0];
}

// writes bias PRE-MULTIPLIED by log2(e)  (softmax is computed in base 2)
__global__ void bias_edge_kernel(const int* __restrict__ adj,
                                 const float* __restrict__ dist,
                                 const float* __restrict__ eoh,
                                 const float* __restrict__ etw,
                                 const float* __restrict__ noedge,
                                 const float* __restrict__ degscale,
                                 const float* __restrict__ gamma) {
    int i = blockIdx.x, b = blockIdx.y;
    float e0 = etw[0], e1 = etw[1], e2 = etw[2], e3 = etw[3];
    float ne = noedge[0], ds = degscale[0], ga = gamma[0];
    float di = g_deg[b * Nn + i];
    float inv_dmx = 1.f / (g_degmax[b] + 1e-6f);
    size_t base = ((size_t)b * Nn + i) * Nn;
    #pragma unroll
    for (int jj = 0; jj < Nn / 256; jj++) {
        int j = threadIdx.x + jj * 256;
        const float* eo = eoh + (base + j) * 4;
        float e = eo[0] * e0 + eo[1] * e1 + eo[2] * e2 + eo[3] * e3 - ga * dist[base + j];
        if (adj[base + j] == 0) e += ne;
        e += ds * (di + g_deg[b * Nn + j]) * inv_dmx;
        g_bias[(size_t)b * Tt * Tt + (size_t)(i + 1) * Tt + (j + 1)] = e * LOG2E;
    }
}

__global__ void bias_fill_kernel(const float* v2n, const float* n2v, const float* vself) {
    int b = blockIdx.x, part = blockIdx.y;
    float a = v2n[0] * LOG2E, c = n2v[0] * LOG2E;
    size_t base = (size_t)b * Tt * Tt;
    int t0 = 1 + part * 192;
    for (int t = t0 + threadIdx.x; t < t0 + 192 && t < Tt; t += 256) {
        g_bias[base + t]              = a;
        g_bias[base + (size_t)t * Tt] = c;
    }
    if (part == 0 && threadIdx.x == 0) g_bias[base] = vself[0] * LOG2E;
}

// ---------------------------------------------------------------------------
__global__ void proj_kernel(const float* __restrict__ nf, const float* __restrict__ W,
                            const float* __restrict__ bb, const float* __restrict__ cls) {
    int t = blockIdx.x, b = blockIdx.y, tid = threadIdx.x;
    if (t == 0) { g_x[((size_t)b * Tt) * Dd + tid] = cls[tid]; return; }
    __shared__ float sm[Ff];
    if (tid < Ff) sm[tid] = nf[((size_t)b * Nn + (t - 1)) * Ff + tid];
    __syncthreads();
    float a = bb[tid];
    #pragma unroll 8
    for (int k2 = 0; k2 < Ff; k2++) a = fmaf(sm[k2], W[k2 * Dd + tid], a);
    g_x[((size_t)b * Tt + t) * Dd + tid] = a;
}

// ---------------------------------------------------------------------------
__global__ void ln_kernel(const float* __restrict__ x, const float* __restrict__ g,
                          const float* __restrict__ bb, float* __restrict__ xn) {
    int row  = blockIdx.x * 8 + (threadIdx.x >> 5);
    int lane = threadIdx.x & 31;
    const float* xr = x + (size_t)row * Dd;
    float v[8], s = 0.f, s2 = 0.f;
    #pragma unroll
    for (int k2 = 0; k2 < 8; k2++) {
        v[k2] = xr[lane + 32 * k2];
        s += v[k2]; s2 += v[k2] * v[k2];
    }
    #pragma unroll
    for (int o = 16; o; o >>= 1) {
        s  += __shfl_xor_sync(0xffffffffu, s, o);
        s2 += __shfl_xor_sync(0xffffffffu, s2, o);
    }
    float mean = s * (1.f / Dd);
    float var  = s2 * (1.f / Dd) - mean * mean;
    float rs = rsqrtf(var + 1e-5f);
    float* orow = xn + (size_t)row * Dd;
    #pragma unroll
    for (int k2 = 0; k2 < 8; k2++) {
        int d = lane + 32 * k2;
        orow[d] = roundtf((v[k2] - mean) * rs * g[d] + bb[d]);
    }
}

// ---------------------------------------------------------------------------
// Tensor-core GEMM (R11 champion): BM=128 BN=128 BK=32, 256 thr / 8 warps
// (4x2, warp 32x64), cp.async double-buffered, 2 blocks/SM.
// EPI: 0=round-store  1=GELU round-store  2=residual add
#define GA_STRIDE 36
#define GW_STRIDE 136
#define GEMM_SMEM ((2*128*GA_STRIDE + 2*32*GW_STRIDE) * 4)   // 71.7 KB

template<int EPI>
__device__ __forceinline__ void gemm_body(float* sm,
                                          const float* __restrict__ A,
                                          const float* __restrict__ W,
                                          const float* __restrict__ bias,
                                          const float* __restrict__ Cres,
                                          float* __restrict__ Cout,
                                          int m0, int n0) {
    const int M = Mrows;
    float* As = sm;                         // [2][128][36]
    float* Ws = sm + 2 * 128 * GA_STRIDE;   // [2][32][136]
    int tid = threadIdx.x, w = tid >> 5, lane = tid & 31;
    int g = lane >> 2, t = lane & 3;
    int wm = (w >> 1) * 32, wn = (w & 1) * 64;

    auto issue = [&](int kt, int buf) {
        int k0 = kt * 32;
        float* Ab = As + buf * 128 * GA_STRIDE;
        #pragma unroll
        for (int r = 0; r < 4; r++) {
            int idx = tid + 256 * r;
            int m = idx >> 3, ch = idx & 7;
            bool p = (m0 + m) < M;
            const float* src = A + (size_t)(p ? (m0 + m) : 0) * 256 + k0 + ch * 4;
            cpa16(Ab + m * GA_STRIDE + ch * 4, src, p);
        }
        float* Wb = Ws + buf * 32 * GW_STRIDE;
        #pragma unroll
        for (int r = 0; r < 4; r++) {
            int idx = tid + 256 * r;
            int kk = idx >> 5, ch = idx & 31;
            cpa16(Wb + kk * GW_STRIDE + ch * 4, W + (size_t)(k0 + kk) * 256 + n0 + ch * 4, true);
        }
        CP_COMMIT();
    };

    float acc[2][8][4];
    #pragma unroll
    for (int i = 0; i < 2; i++)
        #pragma unroll
        for (int j = 0; j < 8; j++)
            #pragma unroll
            for (int c = 0; c < 4; c++) acc[i][j][c] = 0.f;

    issue(0, 0);
    for (int kt = 0; kt < 8; kt++) {
        int buf = kt & 1;
        if (kt < 7) { issue(kt + 1, buf ^ 1); CP_WAIT1(); }
        else        { CP_WAIT0(); }
        __syncthreads();
        const unsigned* Ab = (const unsigned*)(As + buf * 128 * GA_STRIDE);
        const unsigned* Wb = (const unsigned*)(Ws + buf * 32 * GW_STRIDE);
        #pragma unroll
        for (int ks = 0; ks < 4; ks++) {
            int kb = ks * 8;
            unsigned a[2][4];
            #pragma unroll
            for (int mf = 0; mf < 2; mf++) {
                int mb = wm + mf * 16;
                a[mf][0] = Ab[(mb + g)     * GA_STRIDE + kb + t];
                a[mf][1] = Ab[(mb + g + 8) * GA_STRIDE + kb + t];
                a[mf][2] = Ab[(mb + g)     * GA_STRIDE + kb + t + 4];
                a[mf][3] = Ab[(mb + g + 8) * GA_STRIDE + kb + t + 4];
            }
            #pragma unroll
            for (int nf = 0; nf < 8; nf++) {
                unsigned b0 = Wb[(kb + t)     * GW_STRIDE + wn + nf * 8 + g];
                unsigned b1 = Wb[(kb + t + 4) * GW_STRIDE + wn + nf * 8 + g];
                #pragma unroll
                for (int mf = 0; mf < 2; mf++)
                    mma_tf32(acc[mf][nf], a[mf][0], a[mf][1], a[mf][2], a[mf][3], b0, b1);
            }
        }
        __syncthreads();
    }
    #pragma unroll
    for (int mf = 0; mf < 2; mf++) {
        int row0 = m0 + wm + mf * 16 + g;
        #pragma unroll
        for (int nf = 0; nf < 8; nf++) {
            int col = n0 + wn + nf * 8 + 2 * t;
            float bv0 = bias[col], bv1 = bias[col + 1];
            #pragma unroll
            for (int half = 0; half < 2; half++) {
                int row = row0 + half * 8;
                if (row >= M) continue;
                float v0 = acc[mf][nf][half * 2 + 0] + bv0;
                float v1 = acc[mf][nf][half * 2 + 1] + bv1;
                float* cp = Cout + (size_t)row * 256 + col;
                if (EPI == 0) { v0 = roundtf(v0); v1 = roundtf(v1); }
                if (EPI == 1) {
                    v0 = roundtf(0.5f * v0 * (1.f + erff(v0 * 0.70710678118654752f)));
                    v1 = roundtf(0.5f * v1 * (1.f + erff(v1 * 0.70710678118654752f)));
                }
                if (EPI == 2) {
                    const float* rp = Cres + (size_t)row * 256 + col;
                    v0 += rp[0]; v1 += rp[1];
                }
                *(float2*)cp = make_float2(v0, v1);
            }
        }
    }
}

template<int EPI>
__global__ void __launch_bounds__(256, 2)
gemm_one(const float* __restrict__ A, const float* __restrict__ W,
         const float* __restrict__ bias, const float* __restrict__ Cres,
         float* __restrict__ Cout) {
    extern __shared__ float sm[];
    gemm_body<EPI>(sm, A, W, bias, Cres, Cout, blockIdx.y * 128, blockIdx.x * 128);
}

__global__ void __launch_bounds__(256, 2)
gemm_qkv(const float* __restrict__ A, const float* __restrict__ Wr,
         const float* bb0, float* c0,
         const float* bb1, float* c1,
         const float* bb2, float* c2) {
    extern __shared__ float sm[];
    int sel = blockIdx.x >> 1;
    int n0 = (blockIdx.x & 1) * 128, m0 = blockIdx.y * 128;
    const float* W  = Wr + (size_t)sel * LDD;
    const float* bb = (sel == 0) ? bb0 : (sel == 1) ? bb1 : bb2;
    float*       C  = (sel == 0) ? c0  : (sel == 1) ? c1  : c2;
    gemm_body<0>(sm, A, W, bb, C, C, m0, n0);
}

// ---------------------------------------------------------------------------
// Flash attention (R11 config + base-2 softmax): 256 thr / 8 warps,
// 128 q rows/block, double-buffered K/V, interior-tile bias fast path,
// act-guard. Bias is pre-scaled by log2e; Q scale folds log2e -> bare EX2.
#define AQ_STRIDE 36
#define AK_STRIDE 36
#define AV_STRIDE 40
#define AP_STRIDE 68
#define ATTN_SMEM ((128*AQ_STRIDE + 2*64*AK_STRIDE + 2*64*AV_STRIDE + 8*16*AP_STRIDE) * 4)

__global__ void __launch_bounds__(256, 2)
attn_tc(const float* __restrict__ q, const float* __restrict__ k,
        const float* __restrict__ v, const float* __restrict__ bias,
        float* __restrict__ out) {
    extern __shared__ float sm[];
    unsigned* Qs = (unsigned*)sm;                         // [128][36]
    float*    Ks = sm + 128 * AQ_STRIDE;                  // [2][64][36]
    float*    Vs = Ks + 2 * 64 * AK_STRIDE;               // [2][64][40]
    unsigned* Ps = (unsigned*)(Vs + 2 * 64 * AV_STRIDE);  // [8][16][68]

    int b = blockIdx.x >> 3, h = blockIdx.x & 7;
    int q0 = blockIdx.y * 128;
    int tid = threadIdx.x, w = tid >> 5, lane = tid & 31;
    int g = lane >> 2, t = lane & 3;

    // (1/sqrt(32)) * log2(e)  — softmax computed in base-2 domain
    const float scale = 0.17677669529663687f * LOG2E;
    const float* kb_ = k + (size_t)b * Tt * Dd + h * 32;
    const float* vb_ = v + (size_t)b * Tt * Dd + h * 32;
    const float* biasb = bias + (size_t)b * Tt * Tt;

    auto issueKV = [&](int jt, int buf) {
        int j0 = jt * 64;
        float* Kb = Ks + buf * 64 * AK_STRIDE;
        float* Vb = Vs + buf * 64 * AV_STRIDE;
        #pragma unroll
        for (int r = 0; r < 2; r++) {
            int idx = tid + 256 * r;
            int key = idx >> 3, ch = idx & 7;
            int gj = j0 + key;
            bool p = gj < Tt;
            size_t off = (size_t)(p ? gj : 0) * 256 + ch * 4;
            cpa16(Kb + key * AK_STRIDE + ch * 4, kb_ + off, p);
            cpa16(Vb + key * AV_STRIDE + ch * 4, vb_ + off, p);
        }
        CP_COMMIT();
    };

    issueKV(0, 0);
    #pragma unroll
    for (int r = 0; r < 4; r++) {
        int idx = tid + 256 * r;
        int m = idx >> 3, k4 = (idx & 7) << 2;
        float4 qv = make_float4(0.f, 0.f, 0.f, 0.f);
        int qr = q0 + m;
        if (qr < Tt) qv = *(const float4*)(q + ((size_t)(b * Tt + qr)) * 256 + h * 32 + k4);
        Qs[m * AQ_STRIDE + k4 + 0] = f2tf(qv.x * scale);
        Qs[m * AQ_STRIDE + k4 + 1] = f2tf(qv.y * scale);
        Qs[m * AQ_STRIDE + k4 + 2] = f2tf(qv.z * scale);
        Qs[m * AQ_STRIDE + k4 + 3] = f2tf(qv.w * scale);
    }
    __syncthreads();
    int mb = w * 16;
    int r0g = q0 + mb + g, r1g = r0g + 8;
    bool act = (q0 + mb) < Tt;
    bool rowsok = r1g < Tt;

    unsigned qa[4][4];
    if (act) {
        #pragma unroll
        for (int ks = 0; ks < 4; ks++) {
            int kb2 = ks * 8;
            qa[ks][0] = Qs[(mb + g)     * AQ_STRIDE + kb2 + t];
            qa[ks][1] = Qs[(mb + g + 8) * AQ_STRIDE + kb2 + t];
            qa[ks][2] = Qs[(mb + g)     * AQ_STRIDE + kb2 + t + 4];
            qa[ks][3] = Qs[(mb + g + 8) * AQ_STRIDE + kb2 + t + 4];
        }
    }

    float mrow[2] = {-1e30f, -1e30f}, lrow[2] = {0.f, 0.f};
    float oacc[4][4];
    #pragma unroll
    for (int i = 0; i < 4; i++)
        #pragma unroll
        for (int c = 0; c < 4; c++) oacc[i][c] = 0.f;

    const int NTILES = (Tt + 63) / 64;  // 13

    for (int jt = 0; jt < NTILES; jt++) {
        int buf = jt & 1;
        int j0 = jt * 64;

        float s[8][4];
        if (act) {
            const float* br0 = biasb + (size_t)r0g * Tt + j0;
            const float* br1 = biasb + (size_t)r1g * Tt + j0;
            if (rowsok && jt < NTILES - 1) {
                #pragma unroll
                for (int nf = 0; nf < 8; nf++) {
                    int col = nf * 8 + 2 * t;
                    s[nf][0] = __ldg(br0 + col);
                    s[nf][1] = __ldg(br0 + col + 1);
                    s[nf][2] = __ldg(br1 + col);
                    s[nf][3] = __ldg(br1 + col + 1);
                }
            } else {
                #pragma unroll
                for (int nf = 0; nf < 8; nf++) {
                    int col = j0 + nf * 8 + 2 * t;
                    bool cok0 = col < Tt, cok1 = (col + 1) < Tt;
                    s[nf][0] = (r0g < Tt && cok0) ? __ldg(biasb + (size_t)r0g * Tt + col)     : -1e30f;
                    s[nf][1] = (r0g < Tt && cok1) ? __ldg(biasb + (size_t)r0g * Tt + col + 1) : -1e30f;
                    s[nf][2] = (rowsok && cok0)   ? __ldg(biasb + (size_t)r1g * Tt + col)     : -1e30f;
                    s[nf][3] = (rowsok && cok1)   ? __ldg(biasb + (size_t)r1g * Tt + col + 1) : -1e30f;
                }
            }
        }

        if (jt + 1 < NTILES) { issueKV(jt + 1, buf ^ 1); CP_WAIT1(); }
        else                 { CP_WAIT0(); }
        __syncthreads();

        if (act) {
            const unsigned* Kb = (const unsigned*)(Ks + buf * 64 * AK_STRIDE);
            const unsigned* Vb = (const unsigned*)(Vs + buf * 64 * AV_STRIDE);

            #pragma unroll
            for (int ks = 0; ks < 4; ks++) {
                int kb2 = ks * 8;
                #pragma unroll
                for (int nf = 0; nf < 8; nf++) {
                    unsigned b0 = Kb[(nf * 8 + g) * AK_STRIDE + kb2 + t];
                    unsigned b1 = Kb[(nf * 8 + g) * AK_STRIDE + kb2 + t + 4];
                    mma_tf32(s[nf], qa[ks][0], qa[ks][1], qa[ks][2], qa[ks][3], b0, b1);
                }
            }
            float tmax[2] = {-1e30f, -1e30f};
            #pragma unroll
            for (int nf = 0; nf < 8; nf++) {
                tmax[0] = fmaxf(tmax[0], fmaxf(s[nf][0], s[nf][1]));
                tmax[1] = fmaxf(tmax[1], fmaxf(s[nf][2], s[nf][3]));
            }
            #pragma unroll
            for (int o = 1; o <= 2; o <<= 1) {
                tmax[0] = fmaxf(tmax[0], __shfl_xor_sync(0xffffffffu, tmax[0], o));
                tmax[1] = fmaxf(tmax[1], __shfl_xor_sync(0xffffffffu, tmax[1], o));
            }
            float mn0 = fmaxf(mrow[0], tmax[0]), mn1 = fmaxf(mrow[1], tmax[1]);
            // base-2 domain: bare EX2, no multiply. First tile: corr underflows to 0.
            float corr0 = ex2(mrow[0] - mn0), corr1 = ex2(mrow[1] - mn1);
            mrow[0] = mn0; mrow[1] = mn1;
            float sum0 = 0.f, sum1 = 0.f;
            #pragma unroll
            for (int nf = 0; nf < 8; nf++) {
                s[nf][0] = ex2(s[nf][0] - mn0); sum0 += s[nf][0];
                s[nf][1] = ex2(s[nf][1] - mn0); sum0 += s[nf][1];
                s[nf][2] = ex2(s[nf][2] - mn1); sum1 += s[nf][2];
                s[nf][3] = ex2(s[nf][3] - mn1); sum1 += s[nf][3];
            }
            #pragma unroll
            for (int o = 1; o <= 2; o <<= 1) {
                sum0 += __shfl_xor_sync(0xffffffffu, sum0, o);
                sum1 += __shfl_xor_sync(0xffffffffu, sum1, o);
            }
            lrow[0] = lrow[0] * corr0 + sum0;
            lrow[1] = lrow[1] * corr1 + sum1;
            #pragma unroll
            for (int i = 0; i < 4; i++) {
                oacc[i][0] *= corr0; oacc[i][1] *= corr0;
                oacc[i][2] *= corr1; oacc[i][3] *= corr1;
            }
            unsigned* Pw = Ps + w * 16 * AP_STRIDE;
            #pragma unroll
            for (int nf = 0; nf < 8; nf++) {
                int col = nf * 8 + 2 * t;
                Pw[g * AP_STRIDE + col]           = f2tf(s[nf][0]);
                Pw[g * AP_STRIDE + col + 1]       = f2tf(s[nf][1]);
                Pw[(g + 8) * AP_STRIDE + col]     = f2tf(s[nf][2]);
                Pw[(g + 8) * AP_STRIDE + col + 1] = f2tf(s[nf][3]);
            }
            __syncwarp();
            #pragma unroll
            for (int ks2 = 0; ks2 < 8; ks2++) {
                int kk = ks2 * 8;
                unsigned a0 = Pw[g * AP_STRIDE + kk + t];
                unsigned a1 = Pw[(g + 8) * AP_STRIDE + kk + t];
                unsigned a2 = Pw[g * AP_STRIDE + kk + t + 4];
                unsigned a3 = Pw[(g + 8) * AP_STRIDE + kk + t + 4];
                #pragma unroll
                for (int nf2 = 0; nf2 < 4; nf2++) {
                    unsigned b0 = Vb[(kk + t)     * AV_STRIDE + nf2 * 8 + g];
                    unsigned b1 = Vb[(kk + t + 4) * AV_STRIDE + nf2 * 8 + g];
                    mma_tf32(oacc[nf2], a0, a1, a2, a3, b0, b1);
                }
            }
        }
        __syncthreads();
    }
    if (act) {
        float inv0 = 1.f / lrow[0], inv1 = 1.f / lrow[1];
        #pragma unroll
        for (int nf2 = 0; nf2 < 4; nf2++) {
            int feat = nf2 * 8 + 2 * t;
            if (r0g < Tt)
                *(float2*)(out + ((size_t)(b * Tt + r0g)) * 256 + h * 32 + feat) =
                    make_float2(roundtf(oacc[nf2][0] * inv0), roundtf(oacc[nf2][1] * inv0));
            if (rowsok)
                *(float2*)(out + ((size_t)(b * Tt + r1g)) * 256 + h * 32 + feat) =
                    make_float2(roundtf(oacc[nf2][2] * inv1), roundtf(oacc[nf2][3] * inv1));
        }
    }
}

// ---------------------------------------------------------------------------
extern "C" void kernel_launch(void* const* d_in, const int* in_sizes, int n_in,
                              void* d_out, int out_size) {
    const float* nf       = (const float*)d_in[0];
    const int*   adj      = (const int*)  d_in[1];
    const float* dist     = (const float*)d_in[2];
    const float* eoh      = (const float*)d_in[3];
    const float* npw      = (const float*)d_in[4];
    const float* npb      = (const float*)d_in[5];
    const float* cls      = (const float*)d_in[6];
    const float* etw      = (const float*)d_in[7];
    const float* noedge   = (const float*)d_in[8];
    const float* degscale = (const float*)d_in[9];
    const float* gamma    = (const float*)d_in[10];
    const float* v2n      = (const float*)d_in[11];
    const float* n2v      = (const float*)d_in[12];
    const float* vself    = (const float*)d_in[13];
    const float* ln1g = (const float*)d_in[14]; const float* ln1b = (const float*)d_in[15];
    const float* qw   = (const float*)d_in[16]; const float* qb   = (const float*)d_in[17];
    const float* kw   = (const float*)d_in[18]; const float* kb   = (const float*)d_in[19];
    const float* vw   = (const float*)d_in[20]; const float* vb   = (const float*)d_in[21];
    const float* ow   = (const float*)d_in[22]; const float* ob   = (const float*)d_in[23];
    const float* ln2g = (const float*)d_in[24]; const float* ln2b = (const float*)d_in[25];
    const float* fc1w = (const float*)d_in[26]; const float* fc1b = (const float*)d_in[27];
    const float* fc2w = (const float*)d_in[28]; const float* fc2b = (const float*)d_in[29];

    float *p_x, *p_xn, *p_q, *p_k, *p_v, *p_att, *p_m1, *p_bias, *p_wr;
    cudaGetSymbolAddress((void**)&p_x,    g_x);
    cudaGetSymbolAddress((void**)&p_xn,   g_xn);
    cudaGetSymbolAddress((void**)&p_q,    g_q);
    cudaGetSymbolAddress((void**)&p_k,    g_k);
    cudaGetSymbolAddress((void**)&p_v,    g_v);
    cudaGetSymbolAddress((void**)&p_att,  g_att);
    cudaGetSymbolAddress((void**)&p_m1,   g_m1);
    cudaGetSymbolAddress((void**)&p_bias, g_bias);
    cudaGetSymbolAddress((void**)&p_wr,   g_wr);

    cudaFuncSetAttribute(gemm_qkv,    cudaFuncAttributeMaxDynamicSharedMemorySize, GEMM_SMEM);
    cudaFuncSetAttribute(gemm_one<1>, cudaFuncAttributeMaxDynamicSharedMemorySize, GEMM_SMEM);
    cudaFuncSetAttribute(gemm_one<2>, cudaFuncAttributeMaxDynamicSharedMemorySize, GEMM_SMEM);
    cudaFuncSetAttribute(attn_tc,     cudaFuncAttributeMaxDynamicSharedMemorySize, ATTN_SMEM);

    roundw_kernel<<<6 * LDD / 256, 256>>>(qw, kw, vw, ow, fc1w, fc2w);
    deg_kernel<<<(Bq * Nn) / 8, 256>>>(adj);
    degmax_kernel<<<Bq, 256>>>();
    bias_edge_kernel<<<dim3(Nn, Bq), 256>>>(adj, dist, eoh, etw, noedge, degscale, gamma);
    bias_fill_kernel<<<dim3(Bq, 4), 256>>>(v2n, n2v, vself);

    proj_kernel<<<dim3(Tt, Bq), 256>>>(nf, npw, npb, cls);

    dim3 ggrid (2, (Mrows + 127) / 128);    // (2, 49)
    dim3 qgrid (6, (Mrows + 127) / 128);    // (6, 49)
    dim3 agrid (Bq * Hh, (Tt + 127) / 128); // (64, 7)
    for (int l = 0; l < Ll; l++) {
        size_t wo = (size_t)l * Dd * Dd;
        size_t bo = (size_t)l * Dd;
        bool last = (l == Ll - 1);
        ln_kernel<<<Mrows / 8, 256>>>(p_x, ln1g + bo, ln1b + bo, p_xn);
        gemm_qkv<<<qgrid, 256, GEMM_SMEM>>>(p_xn, p_wr + wo,
                                            qb + bo, p_q, kb + bo, p_k, vb + bo, p_v);
        attn_tc<<<agrid, 256, ATTN_SMEM>>>(p_q, p_k, p_v, p_bias, p_att);
        gemm_one<2><<<ggrid, 256, GEMM_SMEM>>>(p_att, p_wr + 3 * LDD + wo, ob + bo, p_x, p_x);
        ln_kernel<<<Mrows / 8, 256>>>(p_x, ln2g + bo, ln2b + bo, p_xn);
        gemm_one<1><<<ggrid, 256, GEMM_SMEM>>>(p_xn, p_wr + 4 * LDD + wo, fc1b + bo, p_m1, p_m1);
        gemm_one<2><<<ggrid, 256, GEMM_SMEM>>>(p_m1, p_wr + 5 * LDD + wo, fc2b + bo,
                                               p_x, last ? (float*)d_out : p_x);
    }
}

// round 16
// speedup vs baseline: 1.0233x; 1.0003x over previous
#include <cuda_runtime.h>
#include <math.h>

#define Bq 8
#define Nn 768
#define Tt 769
#define Dd 256
#define Hh 8
#define Ll 6
#define Ff 128
#define Mrows (Bq*Tt)   // 6152
#define LDD (Ll*Dd*Dd)
#define LOG2E 1.4426950408889634f

__device__ float g_bias[Bq*Tt*Tt];   // stored PRE-MULTIPLIED by log2(e)
__device__ float g_x  [Mrows*Dd];
__device__ float g_xn [Mrows*Dd];
__device__ float g_q  [Mrows*Dd];
__device__ float g_k  [Mrows*Dd];
__device__ float g_v  [Mrows*Dd];
__device__ float g_att[Mrows*Dd];
__device__ float g_m1 [Mrows*Dd];
__device__ float g_deg[Bq*Nn];
__device__ unsigned g_degmax_u[Bq]; // float bits; atomicMax (degrees >= 0)
__device__ float g_wr [6*LDD];      // tf32-pre-rounded weights

// ---------------------------------------------------------------------------
__device__ __forceinline__ unsigned f2tf(float x) {
    unsigned u; asm("cvt.rna.tf32.f32 %0, %1;" : "=r"(u) : "f"(x)); return u;
}
__device__ __forceinline__ float roundtf(float x) {
    return __uint_as_float(f2tf(x));
}
__device__ __forceinline__ float ex2(float x) {
    float r; asm("ex2.approx.f32 %0, %1;" : "=f"(r) : "f"(x)); return r;
}
__device__ __forceinline__ void mma_tf32(float* d,
                                         unsigned a0, unsigned a1, unsigned a2, unsigned a3,
                                         unsigned b0, unsigned b1) {
    asm volatile("mma.sync.aligned.m16n8k8.row.col.f32.tf32.tf32.f32 "
                 "{%0,%1,%2,%3}, {%4,%5,%6,%7}, {%8,%9}, {%0,%1,%2,%3};\n"
                 : "+f"(d[0]), "+f"(d[1]), "+f"(d[2]), "+f"(d[3])
                 : "r"(a0), "r"(a1), "r"(a2), "r"(a3), "r"(b0), "r"(b1));
}
__device__ __forceinline__ void cpa16(float* dst, const float* src, bool pred) {
    unsigned d = (unsigned)__cvta_generic_to_shared(dst);
    int sz = pred ? 16 : 0;
    asm volatile("cp.async.ca.shared.global [%0], [%1], 16, %2;\n"
                 :: "r"(d), "l"(src), "r"(sz));
}
#define CP_COMMIT() asm volatile("cp.async.commit_group;\n")
#define CP_WAIT1()  asm volatile("cp.async.wait_group 1;\n")
#define CP_WAIT0()  asm volatile("cp.async.wait_group 0;\n")

// ---------------------------------------------------------------------------
__global__ void roundw_kernel(const float* __restrict__ qw, const float* __restrict__ kw,
                              const float* __restrict__ vw, const float* __restrict__ ow,
                              const float* __restrict__ f1, const float* __restrict__ f2) {
    int idx = blockIdx.x * 256 + threadIdx.x;
    int sel = idx / LDD, off = idx % LDD;
    const float* src = (sel == 0) ? qw : (sel == 1) ? kw : (sel == 2) ? vw :
                       (sel == 3) ? ow : (sel == 4) ? f1 : f2;
    g_wr[idx] = roundtf(src[off]);
}

// ---------------------------------------------------------------------------
// degree + per-batch max fused (atomicMax on float bits; degrees >= 0 so
// uint ordering == float ordering; idempotent across graph replays)
__global__ void deg_kernel(const int* __restrict__ adj) {
    int row  = blockIdx.x * 8 + (threadIdx.x >> 5);
    int lane = threadIdx.x & 31;
    const int* a = adj + (size_t)row * Nn;
    float s = 0.f;
    #pragma unroll
    for (int k2 = 0; k2 < Nn / 32; k2++) s += (float)a[lane + 32 * k2];
    #pragma unroll
    for (int o = 16; o; o >>= 1) s += __shfl_xor_sync(0xffffffffu, s, o);
    if (lane == 0) {
        g_deg[row] = s;
        atomicMax(&g_degmax_u[row / Nn], __float_as_uint(s));
    }
}

// bias edge + border fill fused; writes PRE-MULTIPLIED by log2(e)
__global__ void bias_edge_kernel(const int* __restrict__ adj,
                                 const float* __restrict__ dist,
                                 const float* __restrict__ eoh,
                                 const float* __restrict__ etw,
                                 const float* __restrict__ noedge,
                                 const float* __restrict__ degscale,
                                 const float* __restrict__ gamma,
                                 const float* __restrict__ v2n,
                                 const float* __restrict__ n2v,
                                 const float* __restrict__ vself) {
    int i = blockIdx.x, b = blockIdx.y;
    float e0 = etw[0], e1 = etw[1], e2 = etw[2], e3 = etw[3];
    float ne = noedge[0], ds = degscale[0], ga = gamma[0];
    float di = g_deg[b * Nn + i];
    float inv_dmx = 1.f / (__uint_as_float(g_degmax_u[b]) + 1e-6f);
    size_t base  = ((size_t)b * Nn + i) * Nn;
    size_t brow  = (size_t)b * Tt * Tt + (size_t)(i + 1) * Tt;
    #pragma unroll
    for (int jj = 0; jj < Nn / 256; jj++) {
        int j = threadIdx.x + jj * 256;
        const float* eo = eoh + (base + j) * 4;
        float e = eo[0] * e0 + eo[1] * e1 + eo[2] * e2 + eo[3] * e3 - ga * dist[base + j];
        if (adj[base + j] == 0) e += ne;
        e += ds * (di + g_deg[b * Nn + j]) * inv_dmx;
        g_bias[brow + (j + 1)] = e * LOG2E;
    }
    // border fill: column 0 of this row; block i==0 also fills row 0
    if (threadIdx.x == 0) g_bias[brow] = n2v[0] * LOG2E;
    if (i == 0) {
        size_t b0 = (size_t)b * Tt * Tt;
        float a = v2n[0] * LOG2E;
        #pragma unroll
        for (int jj = 0; jj < Nn / 256; jj++)
            g_bias[b0 + 1 + threadIdx.x + jj * 256] = a;
        if (threadIdx.x == 0) g_bias[b0] = vself[0] * LOG2E;
    }
}

// ---------------------------------------------------------------------------
__global__ void proj_kernel(const float* __restrict__ nf, const float* __restrict__ W,
                            const float* __restrict__ bb, const float* __restrict__ cls) {
    int t = blockIdx.x, b = blockIdx.y, tid = threadIdx.x;
    if (t == 0) { g_x[((size_t)b * Tt) * Dd + tid] = cls[tid]; return; }
    __shared__ float sm[Ff];
    if (tid < Ff) sm[tid] = nf[((size_t)b * Nn + (t - 1)) * Ff + tid];
    __syncthreads();
    float a = bb[tid];
    #pragma unroll 8
    for (int k2 = 0; k2 < Ff; k2++) a = fmaf(sm[k2], W[k2 * Dd + tid], a);
    g_x[((size_t)b * Tt + t) * Dd + tid] = a;
}

// ---------------------------------------------------------------------------
__global__ void ln_kernel(const float* __restrict__ x, const float* __restrict__ g,
                          const float* __restrict__ bb, float* __restrict__ xn) {
    int row  = blockIdx.x * 8 + (threadIdx.x >> 5);
    int lane = threadIdx.x & 31;
    const float* xr = x + (size_t)row * Dd;
    float v[8], s = 0.f, s2 = 0.f;
    #pragma unroll
    for (int k2 = 0; k2 < 8; k2++) {
        v[k2] = xr[lane + 32 * k2];
        s += v[k2]; s2 += v[k2] * v[k2];
    }
    #pragma unroll
    for (int o = 16; o; o >>= 1) {
        s  += __shfl_xor_sync(0xffffffffu, s, o);
        s2 += __shfl_xor_sync(0xffffffffu, s2, o);
    }
    float mean = s * (1.f / Dd);
    float var  = s2 * (1.f / Dd) - mean * mean;
    float rs = rsqrtf(var + 1e-5f);
    float* orow = xn + (size_t)row * Dd;
    #pragma unroll
    for (int k2 = 0; k2 < 8; k2++) {
        int d = lane + 32 * k2;
        orow[d] = roundtf((v[k2] - mean) * rs * g[d] + bb[d]);
    }
}

// ---------------------------------------------------------------------------
// Tensor-core GEMM (champion): BM=128 BN=128 BK=32, 256 thr / 8 warps
// (4x2, warp 32x64), cp.async double-buffered, 2 blocks/SM.
// EPI: 0=round-store  1=GELU round-store  2=residual add
#define GA_STRIDE 36
#define GW_STRIDE 136
#define GEMM_SMEM ((2*128*GA_STRIDE + 2*32*GW_STRIDE) * 4)   // 71.7 KB

template<int EPI>
__device__ __forceinline__ void gemm_body(float* sm,
                                          const float* __restrict__ A,
                                          const float* __restrict__ W,
                                          const float* __restrict__ bias,
                                          const float* __restrict__ Cres,
                                          float* __restrict__ Cout,
                                          int m0, int n0) {
    const int M = Mrows;
    float* As = sm;                         // [2][128][36]
    float* Ws = sm + 2 * 128 * GA_STRIDE;   // [2][32][136]
    int tid = threadIdx.x, w = tid >> 5, lane = tid & 31;
    int g = lane >> 2, t = lane & 3;
    int wm = (w >> 1) * 32, wn = (w & 1) * 64;

    auto issue = [&](int kt, int buf) {
        int k0 = kt * 32;
        float* Ab = As + buf * 128 * GA_STRIDE;
        #pragma unroll
        for (int r = 0; r < 4; r++) {
            int idx = tid + 256 * r;
            int m = idx >> 3, ch = idx & 7;
            bool p = (m0 + m) < M;
            const float* src = A + (size_t)(p ? (m0 + m) : 0) * 256 + k0 + ch * 4;
            cpa16(Ab + m * GA_STRIDE + ch * 4, src, p);
        }
        float* Wb = Ws + buf * 32 * GW_STRIDE;
        #pragma unroll
        for (int r = 0; r < 4; r++) {
            int idx = tid + 256 * r;
            int kk = idx >> 5, ch = idx & 31;
            cpa16(Wb + kk * GW_STRIDE + ch * 4, W + (size_t)(k0 + kk) * 256 + n0 + ch * 4, true);
        }
        CP_COMMIT();
    };

    float acc[2][8][4];
    #pragma unroll
    for (int i = 0; i < 2; i++)
        #pragma unroll
        for (int j = 0; j < 8; j++)
            #pragma unroll
            for (int c = 0; c < 4; c++) acc[i][j][c] = 0.f;

    issue(0, 0);
    for (int kt = 0; kt < 8; kt++) {
        int buf = kt & 1;
        if (kt < 7) { issue(kt + 1, buf ^ 1); CP_WAIT1(); }
        else        { CP_WAIT0(); }
        __syncthreads();
        const unsigned* Ab = (const unsigned*)(As + buf * 128 * GA_STRIDE);
        const unsigned* Wb = (const unsigned*)(Ws + buf * 32 * GW_STRIDE);
        #pragma unroll
        for (int ks = 0; ks < 4; ks++) {
            int kb = ks * 8;
            unsigned a[2][4];
            #pragma unroll
            for (int mf = 0; mf < 2; mf++) {
                int mb = wm + mf * 16;
                a[mf][0] = Ab[(mb + g)     * GA_STRIDE + kb + t];
                a[mf][1] = Ab[(mb + g + 8) * GA_STRIDE + kb + t];
                a[mf][2] = Ab[(mb + g)     * GA_STRIDE + kb + t + 4];
                a[mf][3] = Ab[(mb + g + 8) * GA_STRIDE + kb + t + 4];
            }
            #pragma unroll
            for (int nf = 0; nf < 8; nf++) {
                unsigned b0 = Wb[(kb + t)     * GW_STRIDE + wn + nf * 8 + g];
                unsigned b1 = Wb[(kb + t + 4) * GW_STRIDE + wn + nf * 8 + g];
                #pragma unroll
                for (int mf = 0; mf < 2; mf++)
                    mma_tf32(acc[mf][nf], a[mf][0], a[mf][1], a[mf][2], a[mf][3], b0, b1);
            }
        }
        __syncthreads();
    }
    #pragma unroll
    for (int mf = 0; mf < 2; mf++) {
        int row0 = m0 + wm + mf * 16 + g;
        #pragma unroll
        for (int nf = 0; nf < 8; nf++) {
            int col = n0 + wn + nf * 8 + 2 * t;
            float bv0 = bias[col], bv1 = bias[col + 1];
            #pragma unroll
            for (int half = 0; half < 2; half++) {
                int row = row0 + half * 8;
                if (row >= M) continue;
                float v0 = acc[mf][nf][half * 2 + 0] + bv0;
                float v1 = acc[mf][nf][half * 2 + 1] + bv1;
                float* cp = Cout + (size_t)row * 256 + col;
                if (EPI == 0) { v0 = roundtf(v0); v1 = roundtf(v1); }
                if (EPI == 1) {
                    v0 = roundtf(0.5f * v0 * (1.f + erff(v0 * 0.70710678118654752f)));
                    v1 = roundtf(0.5f * v1 * (1.f + erff(v1 * 0.70710678118654752f)));
                }
                if (EPI == 2) {
                    const float* rp = Cres + (size_t)row * 256 + col;
                    v0 += rp[0]; v1 += rp[1];
                }
                *(float2*)cp = make_float2(v0, v1);
            }
        }
    }
}

template<int EPI>
__global__ void __launch_bounds__(256, 2)
gemm_one(const float* __restrict__ A, const float* __restrict__ W,
         const float* __restrict__ bias, const float* __restrict__ Cres,
         float* __restrict__ Cout) {
    extern __shared__ float sm[];
    gemm_body<EPI>(sm, A, W, bias, Cres, Cout, blockIdx.y * 128, blockIdx.x * 128);
}

__global__ void __launch_bounds__(256, 2)
gemm_qkv(const float* __restrict__ A, const float* __restrict__ Wr,
         const float* bb0, float* c0,
         const float* bb1, float* c1,
         const float* bb2, float* c2) {
    extern __shared__ float sm[];
    int sel = blockIdx.x >> 1;
    int n0 = (blockIdx.x & 1) * 128, m0 = blockIdx.y * 128;
    const float* W  = Wr + (size_t)sel * LDD;
    const float* bb = (sel == 0) ? bb0 : (sel == 1) ? bb1 : bb2;
    float*       C  = (sel == 0) ? c0  : (sel == 1) ? c1  : c2;
    gemm_body<0>(sm, A, W, bb, C, C, m0, n0);
}

// ---------------------------------------------------------------------------
// Flash attention (champion: R11 config + base-2 softmax)
#define AQ_STRIDE 36
#define AK_STRIDE 36
#define AV_STRIDE 40
#define AP_STRIDE 68
#define ATTN_SMEM ((128*AQ_STRIDE + 2*64*AK_STRIDE + 2*64*AV_STRIDE + 8*16*AP_STRIDE) * 4)

__global__ void __launch_bounds__(256, 2)
attn_tc(const float* __restrict__ q, const float* __restrict__ k,
        const float* __restrict__ v, const float* __restrict__ bias,
        float* __restrict__ out) {
    extern __shared__ float sm[];
    unsigned* Qs = (unsigned*)sm;                         // [128][36]
    float*    Ks = sm + 128 * AQ_STRIDE;                  // [2][64][36]
    float*    Vs = Ks + 2 * 64 * AK_STRIDE;               // [2][64][40]
    unsigned* Ps = (unsigned*)(Vs + 2 * 64 * AV_STRIDE);  // [8][16][68]

    int b = blockIdx.x >> 3, h = blockIdx.x & 7;
    int q0 = blockIdx.y * 128;
    int tid = threadIdx.x, w = tid >> 5, lane = tid & 31;
    int g = lane >> 2, t = lane & 3;

    const float scale = 0.17677669529663687f * LOG2E;
    const float* kb_ = k + (size_t)b * Tt * Dd + h * 32;
    const float* vb_ = v + (size_t)b * Tt * Dd + h * 32;
    const float* biasb = bias + (size_t)b * Tt * Tt;

    auto issueKV = [&](int jt, int buf) {
        int j0 = jt * 64;
        float* Kb = Ks + buf * 64 * AK_STRIDE;
        float* Vb = Vs + buf * 64 * AV_STRIDE;
        #pragma unroll
        for (int r = 0; r < 2; r++) {
            int idx = tid + 256 * r;
            int key = idx >> 3, ch = idx & 7;
            int gj = j0 + key;
            bool p = gj < Tt;
            size_t off = (size_t)(p ? gj : 0) * 256 + ch * 4;
            cpa16(Kb + key * AK_STRIDE + ch * 4, kb_ + off, p);
            cpa16(Vb + key * AV_STRIDE + ch * 4, vb_ + off, p);
        }
        CP_COMMIT();
    };

    issueKV(0, 0);
    #pragma unroll
    for (int r = 0; r < 4; r++) {
        int idx = tid + 256 * r;
        int m = idx >> 3, k4 = (idx & 7) << 2;
        float4 qv = make_float4(0.f, 0.f, 0.f, 0.f);
        int qr = q0 + m;
        if (qr < Tt) qv = *(const float4*)(q + ((size_t)(b * Tt + qr)) * 256 + h * 32 + k4);
        Qs[m * AQ_STRIDE + k4 + 0] = f2tf(qv.x * scale);
        Qs[m * AQ_STRIDE + k4 + 1] = f2tf(qv.y * scale);
        Qs[m * AQ_STRIDE + k4 + 2] = f2tf(qv.z * scale);
        Qs[m * AQ_STRIDE + k4 + 3] = f2tf(qv.w * scale);
    }
    __syncthreads();
    int mb = w * 16;
    int r0g = q0 + mb + g, r1g = r0g + 8;
    bool act = (q0 + mb) < Tt;
    bool rowsok = r1g < Tt;

    unsigned qa[4][4];
    if (act) {
        #pragma unroll
        for (int ks = 0; ks < 4; ks++) {
            int kb2 = ks * 8;
            qa[ks][0] = Qs[(mb + g)     * AQ_STRIDE + kb2 + t];
            qa[ks][1] = Qs[(mb + g + 8) * AQ_STRIDE + kb2 + t];
            qa[ks][2] = Qs[(mb + g)     * AQ_STRIDE + kb2 + t + 4];
            qa[ks][3] = Qs[(mb + g + 8) * AQ_STRIDE + kb2 + t + 4];
        }
    }

    float mrow[2] = {-1e30f, -1e30f}, lrow[2] = {0.f, 0.f};
    float oacc[4][4];
    #pragma unroll
    for (int i = 0; i < 4; i++)
        #pragma unroll
        for (int c = 0; c < 4; c++) oacc[i][c] = 0.f;

    const int NTILES = (Tt + 63) / 64;  // 13

    for (int jt = 0; jt < NTILES; jt++) {
        int buf = jt & 1;
        int j0 = jt * 64;

        float s[8][4];
        if (act) {
            const float* br0 = biasb + (size_t)r0g * Tt + j0;
            const float* br1 = biasb + (size_t)r1g * Tt + j0;
            if (rowsok && jt < NTILES - 1) {
                #pragma unroll
                for (int nf = 0; nf < 8; nf++) {
                    int col = nf * 8 + 2 * t;
                    s[nf][0] = __ldg(br0 + col);
                    s[nf][1] = __ldg(br0 + col + 1);
                    s[nf][2] = __ldg(br1 + col);
                    s[nf][3] = __ldg(br1 + col + 1);
                }
            } else {
                #pragma unroll
                for (int nf = 0; nf < 8; nf++) {
                    int col = j0 + nf * 8 + 2 * t;
                    bool cok0 = col < Tt, cok1 = (col + 1) < Tt;
                    s[nf][0] = (r0g < Tt && cok0) ? __ldg(biasb + (size_t)r0g * Tt + col)     : -1e30f;
                    s[nf][1] = (r0g < Tt && cok1) ? __ldg(biasb + (size_t)r0g * Tt + col + 1) : -1e30f;
                    s[nf][2] = (rowsok && cok0)   ? __ldg(biasb + (size_t)r1g * Tt + col)     : -1e30f;
                    s[nf][3] = (rowsok && cok1)   ? __ldg(biasb + (size_t)r1g * Tt + col + 1) : -1e30f;
                }
            }
        }

        if (jt + 1 < NTILES) { issueKV(jt + 1, buf ^ 1); CP_WAIT1(); }
        else                 { CP_WAIT0(); }
        __syncthreads();

        if (act) {
            const unsigned* Kb = (const unsigned*)(Ks + buf * 64 * AK_STRIDE);
            const unsigned* Vb = (const unsigned*)(Vs + buf * 64 * AV_STRIDE);

            #pragma unroll
            for (int ks = 0; ks < 4; ks++) {
                int kb2 = ks * 8;
                #pragma unroll
                for (int nf = 0; nf < 8; nf++) {
                    unsigned b0 = Kb[(nf * 8 + g) * AK_STRIDE + kb2 + t];
                    unsigned b1 = Kb[(nf * 8 + g) * AK_STRIDE + kb2 + t + 4];
                    mma_tf32(s[nf], qa[ks][0], qa[ks][1], qa[ks][2], qa[ks][3], b0, b1);
                }
            }
            float tmax[2] = {-1e30f, -1e30f};
            #pragma unroll
            for (int nf = 0; nf < 8; nf++) {
                tmax[0] = fmaxf(tmax[0], fmaxf(s[nf][0], s[nf][1]));
                tmax[1] = fmaxf(tmax[1], fmaxf(s[nf][2], s[nf][3]));
            }
            #pragma unroll
            for (int o = 1; o <= 2; o <<= 1) {
                tmax[0] = fmaxf(tmax[0], __shfl_xor_sync(0xffffffffu, tmax[0], o));
                tmax[1] = fmaxf(tmax[1], __shfl_xor_sync(0xffffffffu, tmax[1], o));
            }
            float mn0 = fmaxf(mrow[0], tmax[0]), mn1 = fmaxf(mrow[1], tmax[1]);
            float corr0 = ex2(mrow[0] - mn0), corr1 = ex2(mrow[1] - mn1);
            mrow[0] = mn0; mrow[1] = mn1;
            float sum0 = 0.f, sum1 = 0.f;
            #pragma unroll
            for (int nf = 0; nf < 8; nf++) {
                s[nf][0] = ex2(s[nf][0] - mn0); sum0 += s[nf][0];
                s[nf][1] = ex2(s[nf][1] - mn0); sum0 += s[nf][1];
                s[nf][2] = ex2(s[nf][2] - mn1); sum1 += s[nf][2];
                s[nf][3] = ex2(s[nf][3] - mn1); sum1 += s[nf][3];
            }
            #pragma unroll
            for (int o = 1; o <= 2; o <<= 1) {
                sum0 += __shfl_xor_sync(0xffffffffu, sum0, o);
                sum1 += __shfl_xor_sync(0xffffffffu, sum1, o);
            }
            lrow[0] = lrow[0] * corr0 + sum0;
            lrow[1] = lrow[1] * corr1 + sum1;
            #pragma unroll
            for (int i = 0; i < 4; i++) {
                oacc[i][0] *= corr0; oacc[i][1] *= corr0;
                oacc[i][2] *= corr1; oacc[i][3] *= corr1;
            }
            unsigned* Pw = Ps + w * 16 * AP_STRIDE;
            #pragma unroll
            for (int nf = 0; nf < 8; nf++) {
                int col = nf * 8 + 2 * t;
                Pw[g * AP_STRIDE + col]           = f2tf(s[nf][0]);
                Pw[g * AP_STRIDE + col + 1]       = f2tf(s[nf][1]);
                Pw[(g + 8) * AP_STRIDE + col]     = f2tf(s[nf][2]);
                Pw[(g + 8) * AP_STRIDE + col + 1] = f2tf(s[nf][3]);
            }
            __syncwarp();
            #pragma unroll
            for (int ks2 = 0; ks2 < 8; ks2++) {
                int kk = ks2 * 8;
                unsigned a0 = Pw[g * AP_STRIDE + kk + t];
                unsigned a1 = Pw[(g + 8) * AP_STRIDE + kk + t];
                unsigned a2 = Pw[g * AP_STRIDE + kk + t + 4];
                unsigned a3 = Pw[(g + 8) * AP_STRIDE + kk + t + 4];
                #pragma unroll
                for (int nf2 = 0; nf2 < 4; nf2++) {
                    unsigned b0 = Vb[(kk + t)     * AV_STRIDE + nf2 * 8 + g];
                    unsigned b1 = Vb[(kk + t + 4) * AV_STRIDE + nf2 * 8 + g];
                    mma_tf32(oacc[nf2], a0, a1, a2, a3, b0, b1);
                }
            }
        }
        __syncthreads();
    }
    if (act) {
        float inv0 = 1.f / lrow[0], inv1 = 1.f / lrow[1];
        #pragma unroll
        for (int nf2 = 0; nf2 < 4; nf2++) {
            int feat = nf2 * 8 + 2 * t;
            if (r0g < Tt)
                *(float2*)(out + ((size_t)(b * Tt + r0g)) * 256 + h * 32 + feat) =
                    make_float2(roundtf(oacc[nf2][0] * inv0), roundtf(oacc[nf2][1] * inv0));
            if (rowsok)
                *(float2*)(out + ((size_t)(b * Tt + r1g)) * 256 + h * 32 + feat) =
                    make_float2(roundtf(oacc[nf2][2] * inv1), roundtf(oacc[nf2][3] * inv1));
        }
    }
}

// ---------------------------------------------------------------------------
extern "C" void kernel_launch(void* const* d_in, const int* in_sizes, int n_in,
                              void* d_out, int out_size) {
    const float* nf       = (const float*)d_in[0];
    const int*   adj      = (const int*)  d_in[1];
    const float* dist     = (const float*)d_in[2];
    const float* eoh      = (const float*)d_in[3];
    const float* npw      = (const float*)d_in[4];
    const float* npb      = (const float*)d_in[5];
    const float* cls      = (const float*)d_in[6];
    const float* etw      = (const float*)d_in[7];
    const float* noedge   = (const float*)d_in[8];
    const float* degscale = (const float*)d_in[9];
    const float* gamma    = (const float*)d_in[10];
    const float* v2n      = (const float*)d_in[11];
    const float* n2v      = (const float*)d_in[12];
    const float* vself    = (const float*)d_in[13];
    const float* ln1g = (const float*)d_in[14]; const float* ln1b = (const float*)d_in[15];
    const float* qw   = (const float*)d_in[16]; const float* qb   = (const float*)d_in[17];
    const float* kw   = (const float*)d_in[18]; const float* kb   = (const float*)d_in[19];
    const float* vw   = (const float*)d_in[20]; const float* vb   = (const float*)d_in[21];
    const float* ow   = (const float*)d_in[22]; const float* ob   = (const float*)d_in[23];
    const float* ln2g = (const float*)d_in[24]; const float* ln2b = (const float*)d_in[25];
    const float* fc1w = (const float*)d_in[26]; const float* fc1b = (const float*)d_in[27];
    const float* fc2w = (const float*)d_in[28]; const float* fc2b = (const float*)d_in[29];

    float *p_x, *p_xn, *p_q, *p_k, *p_v, *p_att, *p_m1, *p_bias, *p_wr;
    cudaGetSymbolAddress((void**)&p_x,    g_x);
    cudaGetSymbolAddress((void**)&p_xn,   g_xn);
    cudaGetSymbolAddress((void**)&p_q,    g_q);
    cudaGetSymbolAddress((void**)&p_k,    g_k);
    cudaGetSymbolAddress((void**)&p_v,    g_v);
    cudaGetSymbolAddress((void**)&p_att,  g_att);
    cudaGetSymbolAddress((void**)&p_m1,   g_m1);
    cudaGetSymbolAddress((void**)&p_bias, g_bias);
    cudaGetSymbolAddress((void**)&p_wr,   g_wr);

    cudaFuncSetAttribute(gemm_qkv,    cudaFuncAttributeMaxDynamicSharedMemorySize, GEMM_SMEM);
    cudaFuncSetAttribute(gemm_one<1>, cudaFuncAttributeMaxDynamicSharedMemorySize, GEMM_SMEM);
    cudaFuncSetAttribute(gemm_one<2>, cudaFuncAttributeMaxDynamicSharedMemorySize, GEMM_SMEM);
    cudaFuncSetAttribute(attn_tc,     cudaFuncAttributeMaxDynamicSharedMemorySize, ATTN_SMEM);

    roundw_kernel<<<6 * LDD / 256, 256>>>(qw, kw, vw, ow, fc1w, fc2w);
    deg_kernel<<<(Bq * Nn) / 8, 256>>>(adj);
    bias_edge_kernel<<<dim3(Nn, Bq), 256>>>(adj, dist, eoh, etw, noedge, degscale, gamma,
                                            v2n, n2v, vself);

    proj_kernel<<<dim3(Tt, Bq), 256>>>(nf, npw, npb, cls);

    dim3 ggrid (2, (Mrows + 127) / 128);    // (2, 49)
    dim3 qgrid (6, (Mrows + 127) / 128);    // (6, 49)
    dim3 agrid (Bq * Hh, (Tt + 127) / 128); // (64, 7)
    for (int l = 0; l < Ll; l++) {
        size_t wo = (size_t)l * Dd * Dd;
        size_t bo = (size_t)l * Dd;
        bool last = (l == Ll - 1);
        ln_kernel<<<Mrows / 8, 256>>>(p_x, ln1g + bo, ln1b + bo, p_xn);
        gemm_qkv<<<qgrid, 256, GEMM_SMEM>>>(p_xn, p_wr + wo,
                                            qb + bo, p_q, kb + bo, p_k, vb + bo, p_v);
        attn_tc<<<agrid, 256, ATTN_SMEM>>>(p_q, p_k, p_v, p_bias, p_att);
        gemm_one<2><<<ggrid, 256, GEMM_SMEM>>>(p_att, p_wr + 3 * LDD + wo, ob + bo, p_x, p_x);
        ln_kernel<<<Mrows / 8, 256>>>(p_x, ln2g + bo, ln2b + bo, p_xn);
        gemm_one<1><<<ggrid, 256, GEMM_SMEM>>>(p_xn, p_wr + 4 * LDD + wo, fc1b + bo, p_m1, p_m1);
        gemm_one<2><<<ggrid, 256, GEMM_SMEM>>>(p_m1, p_wr + 5 * LDD + wo, fc2b + bo,
                                               p_x, last ? (float*)d_out : p_x);
    }
}

// round 17
// speedup vs baseline: 1.0528x; 1.0288x over previous
#include <cuda_runtime.h>
#include <math.h>

#define Bq 8
#define Nn 768
#define Tt 769
#define Dd 256
#define Hh 8
#define Ll 6
#define Ff 128
#define Mrows (Bq*Tt)   // 6152
#define LDD (Ll*Dd*Dd)
#define LOG2E 1.4426950408889634f

__device__ float g_bias[Bq*Tt*Tt];   // stored PRE-MULTIPLIED by log2(e)
__device__ float g_x  [Mrows*Dd];
__device__ float g_xn [Mrows*Dd];
__device__ float g_q  [Mrows*Dd];
__device__ float g_k  [Mrows*Dd];
__device__ float g_v  [Mrows*Dd];
__device__ float g_att[Mrows*Dd];
__device__ float g_m1 [Mrows*Dd];
__device__ float g_deg[Bq*Nn];
__device__ unsigned g_degmax_u[Bq];
__device__ float g_wr  [6*LDD];      // tf32-pre-rounded weights
__device__ float g_npwr[Ff*Dd];      // tf32-pre-rounded node_proj_w

// ---------------------------------------------------------------------------
__device__ __forceinline__ unsigned f2tf(float x) {
    unsigned u; asm("cvt.rna.tf32.f32 %0, %1;" : "=r"(u) : "f"(x)); return u;
}
__device__ __forceinline__ float roundtf(float x) {
    return __uint_as_float(f2tf(x));
}
__device__ __forceinline__ float ex2(float x) {
    float r; asm("ex2.approx.f32 %0, %1;" : "=f"(r) : "f"(x)); return r;
}
__device__ __forceinline__ void mma_tf32(float* d,
                                         unsigned a0, unsigned a1, unsigned a2, unsigned a3,
                                         unsigned b0, unsigned b1) {
    asm volatile("mma.sync.aligned.m16n8k8.row.col.f32.tf32.tf32.f32 "
                 "{%0,%1,%2,%3}, {%4,%5,%6,%7}, {%8,%9}, {%0,%1,%2,%3};\n"
                 : "+f"(d[0]), "+f"(d[1]), "+f"(d[2]), "+f"(d[3])
                 : "r"(a0), "r"(a1), "r"(a2), "r"(a3), "r"(b0), "r"(b1));
}
__device__ __forceinline__ void cpa16(float* dst, const float* src, bool pred) {
    unsigned d = (unsigned)__cvta_generic_to_shared(dst);
    int sz = pred ? 16 : 0;
    asm volatile("cp.async.ca.shared.global [%0], [%1], 16, %2;\n"
                 :: "r"(d), "l"(src), "r"(sz));
}
#define CP_COMMIT() asm volatile("cp.async.commit_group;\n")
#define CP_WAIT1()  asm volatile("cp.async.wait_group 1;\n")
#define CP_WAIT0()  asm volatile("cp.async.wait_group 0;\n")

// ---------------------------------------------------------------------------
__global__ void roundw_kernel(const float* __restrict__ qw, const float* __restrict__ kw,
                              const float* __restrict__ vw, const float* __restrict__ ow,
                              const float* __restrict__ f1, const float* __restrict__ f2) {
    int idx = blockIdx.x * 256 + threadIdx.x;
    int sel = idx / LDD, off = idx % LDD;
    const float* src = (sel == 0) ? qw : (sel == 1) ? kw : (sel == 2) ? vw :
                       (sel == 3) ? ow : (sel == 4) ? f1 : f2;
    g_wr[idx] = roundtf(src[off]);
}
__global__ void roundnpw_kernel(const float* __restrict__ npw) {
    int idx = blockIdx.x * 256 + threadIdx.x;
    g_npwr[idx] = roundtf(npw[idx]);
}

// ---------------------------------------------------------------------------
__global__ void deg_kernel(const int* __restrict__ adj) {
    int row  = blockIdx.x * 8 + (threadIdx.x >> 5);
    int lane = threadIdx.x & 31;
    const int* a = adj + (size_t)row * Nn;
    float s = 0.f;
    #pragma unroll
    for (int k2 = 0; k2 < Nn / 32; k2++) s += (float)a[lane + 32 * k2];
    #pragma unroll
    for (int o = 16; o; o >>= 1) s += __shfl_xor_sync(0xffffffffu, s, o);
    if (lane == 0) {
        g_deg[row] = s;
        atomicMax(&g_degmax_u[row / Nn], __float_as_uint(s));
    }
}

__global__ void bias_edge_kernel(const int* __restrict__ adj,
                                 const float* __restrict__ dist,
                                 const float* __restrict__ eoh,
                                 const float* __restrict__ etw,
                                 const float* __restrict__ noedge,
                                 const float* __restrict__ degscale,
                                 const float* __restrict__ gamma,
                                 const float* __restrict__ v2n,
                                 const float* __restrict__ n2v,
                                 const float* __restrict__ vself) {
    int i = blockIdx.x, b = blockIdx.y;
    float e0 = etw[0], e1 = etw[1], e2 = etw[2], e3 = etw[3];
    float ne = noedge[0], ds = degscale[0], ga = gamma[0];
    float di = g_deg[b * Nn + i];
    float inv_dmx = 1.f / (__uint_as_float(g_degmax_u[b]) + 1e-6f);
    size_t base  = ((size_t)b * Nn + i) * Nn;
    size_t brow  = (size_t)b * Tt * Tt + (size_t)(i + 1) * Tt;
    #pragma unroll
    for (int jj = 0; jj < Nn / 256; jj++) {
        int j = threadIdx.x + jj * 256;
        const float* eo = eoh + (base + j) * 4;
        float e = eo[0] * e0 + eo[1] * e1 + eo[2] * e2 + eo[3] * e3 - ga * dist[base + j];
        if (adj[base + j] == 0) e += ne;
        e += ds * (di + g_deg[b * Nn + j]) * inv_dmx;
        g_bias[brow + (j + 1)] = e * LOG2E;
    }
    if (threadIdx.x == 0) g_bias[brow] = n2v[0] * LOG2E;
    if (i == 0) {
        size_t b0 = (size_t)b * Tt * Tt;
        float a = v2n[0] * LOG2E;
        #pragma unroll
        for (int jj = 0; jj < Nn / 256; jj++)
            g_bias[b0 + 1 + threadIdx.x + jj * 256] = a;
        if (threadIdx.x == 0) g_bias[b0] = vself[0] * LOG2E;
    }
}

// ---------------------------------------------------------------------------
__global__ void ln_kernel(const float* __restrict__ x, const float* __restrict__ g,
                          const float* __restrict__ bb, float* __restrict__ xn) {
    int row  = blockIdx.x * 8 + (threadIdx.x >> 5);
    int lane = threadIdx.x & 31;
    const float* xr = x + (size_t)row * Dd;
    float v[8], s = 0.f, s2 = 0.f;
    #pragma unroll
    for (int k2 = 0; k2 < 8; k2++) {
        v[k2] = xr[lane + 32 * k2];
        s += v[k2]; s2 += v[k2] * v[k2];
    }
    #pragma unroll
    for (int o = 16; o; o >>= 1) {
        s  += __shfl_xor_sync(0xffffffffu, s, o);
        s2 += __shfl_xor_sync(0xffffffffu, s2, o);
    }
    float mean = s * (1.f / Dd);
    float var  = s2 * (1.f / Dd) - mean * mean;
    float rs = rsqrtf(var + 1e-5f);
    float* orow = xn + (size_t)row * Dd;
    #pragma unroll
    for (int k2 = 0; k2 < 8; k2++) {
        int d = lane + 32 * k2;
        orow[d] = roundtf((v[k2] - mean) * rs * g[d] + bb[d]);
    }
}

// ---------------------------------------------------------------------------
// Tensor-core GEMM (champion): BM=128 BN=128 BK=32, 256 thr / 8 warps
// (4x2, warp 32x64), cp.async double-buffered, 2 blocks/SM.
#define GA_STRIDE 36
#define GW_STRIDE 136
#define GEMM_SMEM ((2*128*GA_STRIDE + 2*32*GW_STRIDE) * 4)   // 71.7 KB

template<int EPI>
__device__ __forceinline__ void gemm_body(float* sm,
                                          const float* __restrict__ A,
                                          const float* __restrict__ W,
                                          const float* __restrict__ bias,
                                          const float* __restrict__ Cres,
                                          float* __restrict__ Cout,
                                          int m0, int n0) {
    const int M = Mrows;
    float* As = sm;
    float* Ws = sm + 2 * 128 * GA_STRIDE;
    int tid = threadIdx.x, w = tid >> 5, lane = tid & 31;
    int g = lane >> 2, t = lane & 3;
    int wm = (w >> 1) * 32, wn = (w & 1) * 64;

    auto issue = [&](int kt, int buf) {
        int k0 = kt * 32;
        float* Ab = As + buf * 128 * GA_STRIDE;
        #pragma unroll
        for (int r = 0; r < 4; r++) {
            int idx = tid + 256 * r;
            int m = idx >> 3, ch = idx & 7;
            bool p = (m0 + m) < M;
            const float* src = A + (size_t)(p ? (m0 + m) : 0) * 256 + k0 + ch * 4;
            cpa16(Ab + m * GA_STRIDE + ch * 4, src, p);
        }
        float* Wb = Ws + buf * 32 * GW_STRIDE;
        #pragma unroll
        for (int r = 0; r < 4; r++) {
            int idx = tid + 256 * r;
            int kk = idx >> 5, ch = idx & 31;
            cpa16(Wb + kk * GW_STRIDE + ch * 4, W + (size_t)(k0 + kk) * 256 + n0 + ch * 4, true);
        }
        CP_COMMIT();
    };

    float acc[2][8][4];
    #pragma unroll
    for (int i = 0; i < 2; i++)
        #pragma unroll
        for (int j = 0; j < 8; j++)
            #pragma unroll
            for (int c = 0; c < 4; c++) acc[i][j][c] = 0.f;

    issue(0, 0);
    for (int kt = 0; kt < 8; kt++) {
        int buf = kt & 1;
        if (kt < 7) { issue(kt + 1, buf ^ 1); CP_WAIT1(); }
        else        { CP_WAIT0(); }
        __syncthreads();
        const unsigned* Ab = (const unsigned*)(As + buf * 128 * GA_STRIDE);
        const unsigned* Wb = (const unsigned*)(Ws + buf * 32 * GW_STRIDE);
        #pragma unroll
        for (int ks = 0; ks < 4; ks++) {
            int kb = ks * 8;
            unsigned a[2][4];
            #pragma unroll
            for (int mf = 0; mf < 2; mf++) {
                int mb = wm + mf * 16;
                a[mf][0] = Ab[(mb + g)     * GA_STRIDE + kb + t];
                a[mf][1] = Ab[(mb + g + 8) * GA_STRIDE + kb + t];
                a[mf][2] = Ab[(mb + g)     * GA_STRIDE + kb + t + 4];
                a[mf][3] = Ab[(mb + g + 8) * GA_STRIDE + kb + t + 4];
            }
            #pragma unroll
            for (int nf = 0; nf < 8; nf++) {
                unsigned b0 = Wb[(kb + t)     * GW_STRIDE + wn + nf * 8 + g];
                unsigned b1 = Wb[(kb + t + 4) * GW_STRIDE + wn + nf * 8 + g];
                #pragma unroll
                for (int mf = 0; mf < 2; mf++)
                    mma_tf32(acc[mf][nf], a[mf][0], a[mf][1], a[mf][2], a[mf][3], b0, b1);
            }
        }
        __syncthreads();
    }
    #pragma unroll
    for (int mf = 0; mf < 2; mf++) {
        int row0 = m0 + wm + mf * 16 + g;
        #pragma unroll
        for (int nf = 0; nf < 8; nf++) {
            int col = n0 + wn + nf * 8 + 2 * t;
            float bv0 = bias[col], bv1 = bias[col + 1];
            #pragma unroll
            for (int half = 0; half < 2; half++) {
                int row = row0 + half * 8;
                if (row >= M) continue;
                float v0 = acc[mf][nf][half * 2 + 0] + bv0;
                float v1 = acc[mf][nf][half * 2 + 1] + bv1;
                float* cp = Cout + (size_t)row * 256 + col;
                if (EPI == 0) { v0 = roundtf(v0); v1 = roundtf(v1); }
                if (EPI == 1) {
                    v0 = roundtf(0.5f * v0 * (1.f + erff(v0 * 0.70710678118654752f)));
                    v1 = roundtf(0.5f * v1 * (1.f + erff(v1 * 0.70710678118654752f)));
                }
                if (EPI == 2) {
                    const float* rp = Cres + (size_t)row * 256 + col;
                    v0 += rp[0]; v1 += rp[1];
                }
                *(float2*)cp = make_float2(v0, v1);
            }
        }
    }
}

template<int EPI>
__global__ void __launch_bounds__(256, 2)
gemm_one(const float* __restrict__ A, const float* __restrict__ W,
         const float* __restrict__ bias, const float* __restrict__ Cres,
         float* __restrict__ Cout) {
    extern __shared__ float sm[];
    gemm_body<EPI>(sm, A, W, bias, Cres, Cout, blockIdx.y * 128, blockIdx.x * 128);
}

__global__ void __launch_bounds__(256, 2)
gemm_qkv(const float* __restrict__ A, const float* __restrict__ Wr,
         const float* bb0, float* c0,
         const float* bb1, float* c1,
         const float* bb2, float* c2) {
    extern __shared__ float sm[];
    int sel = blockIdx.x >> 1;
    int n0 = (blockIdx.x & 1) * 128, m0 = blockIdx.y * 128;
    const float* W  = Wr + (size_t)sel * LDD;
    const float* bb = (sel == 0) ? bb0 : (sel == 1) ? bb1 : bb2;
    float*       C  = (sel == 0) ? c0  : (sel == 1) ? c1  : c2;
    gemm_body<0>(sm, A, W, bb, C, C, m0, n0);
}

// ---------------------------------------------------------------------------
// Projection GEMM: x[b*Tt+t] = (t==0) ? cls : nf[b*Nn+t-1] @ npw + npb.
// BM=128 BN=128, K=128 (4 BK-tiles). nf rows remapped through the cls offset;
// A fragments cvt'd to tf32 (RNA) at read; W pre-rounded (g_npwr).
__global__ void __launch_bounds__(256, 2)
proj_gemm(const float* __restrict__ nf, const float* __restrict__ Wr,
          const float* __restrict__ bb, const float* __restrict__ cls,
          float* __restrict__ Cout) {
    extern __shared__ float sm[];
    const int M = Mrows;
    int m0 = blockIdx.y * 128, n0 = blockIdx.x * 128;
    float* As = sm;                         // [2][128][36]
    float* Ws = sm + 2 * 128 * GA_STRIDE;   // [2][32][136]
    int tid = threadIdx.x, w = tid >> 5, lane = tid & 31;
    int g = lane >> 2, t = lane & 3;
    int wm = (w >> 1) * 32, wn = (w & 1) * 64;

    auto issue = [&](int kt, int buf) {
        int k0 = kt * 32;
        float* Ab = As + buf * 128 * GA_STRIDE;
        #pragma unroll
        for (int r = 0; r < 4; r++) {
            int idx = tid + 256 * r;
            int m = idx >> 3, ch = idx & 7;
            int grow = m0 + m;
            int bb_ = grow / Tt, tl = grow - bb_ * Tt;
            bool p = (grow < M) && (tl > 0);
            int srow = bb_ * Nn + (tl - 1);
            const float* src = nf + (size_t)(p ? srow : 0) * Ff + k0 + ch * 4;
            cpa16(Ab + m * GA_STRIDE + ch * 4, src, p);   // zero-fills t==0 rows
        }
        float* Wb = Ws + buf * 32 * GW_STRIDE;
        #pragma unroll
        for (int r = 0; r < 4; r++) {
            int idx = tid + 256 * r;
            int kk = idx >> 5, ch = idx & 31;
            cpa16(Wb + kk * GW_STRIDE + ch * 4, Wr + (size_t)(k0 + kk) * 256 + n0 + ch * 4, true);
        }
        CP_COMMIT();
    };

    float acc[2][8][4];
    #pragma unroll
    for (int i = 0; i < 2; i++)
        #pragma unroll
        for (int j = 0; j < 8; j++)
            #pragma unroll
            for (int c = 0; c < 4; c++) acc[i][j][c] = 0.f;

    issue(0, 0);
    for (int kt = 0; kt < 4; kt++) {
        int buf = kt & 1;
        if (kt < 3) { issue(kt + 1, buf ^ 1); CP_WAIT1(); }
        else        { CP_WAIT0(); }
        __syncthreads();
        const float*    Abf = As + buf * 128 * GA_STRIDE;
        const unsigned* Wb  = (const unsigned*)(Ws + buf * 32 * GW_STRIDE);
        #pragma unroll
        for (int ks = 0; ks < 4; ks++) {
            int kb = ks * 8;
            unsigned a[2][4];
            #pragma unroll
            for (int mf = 0; mf < 2; mf++) {
                int mb = wm + mf * 16;
                a[mf][0] = f2tf(Abf[(mb + g)     * GA_STRIDE + kb + t]);
                a[mf][1] = f2tf(Abf[(mb + g + 8) * GA_STRIDE + kb + t]);
                a[mf][2] = f2tf(Abf[(mb + g)     * GA_STRIDE + kb + t + 4]);
                a[mf][3] = f2tf(Abf[(mb + g + 8) * GA_STRIDE + kb + t + 4]);
            }
            #pragma unroll
            for (int nf2 = 0; nf2 < 8; nf2++) {
                unsigned b0 = Wb[(kb + t)     * GW_STRIDE + wn + nf2 * 8 + g];
                unsigned b1 = Wb[(kb + t + 4) * GW_STRIDE + wn + nf2 * 8 + g];
                #pragma unroll
                for (int mf = 0; mf < 2; mf++)
                    mma_tf32(acc[mf][nf2], a[mf][0], a[mf][1], a[mf][2], a[mf][3], b0, b1);
            }
        }
        __syncthreads();
    }
    #pragma unroll
    for (int mf = 0; mf < 2; mf++) {
        int row0 = m0 + wm + mf * 16 + g;
        #pragma unroll
        for (int nf2 = 0; nf2 < 8; nf2++) {
            int col = n0 + wn + nf2 * 8 + 2 * t;
            float bv0 = bb[col], bv1 = bb[col + 1];
            float c0 = cls[col], c1 = cls[col + 1];
            #pragma unroll
            for (int half = 0; half < 2; half++) {
                int row = row0 + half * 8;
                if (row >= M) continue;
                int bq = row / Tt, tl = row - bq * Tt;
                float v0 = (tl == 0) ? c0 : acc[mf][nf2][half * 2 + 0] + bv0;
                float v1 = (tl == 0) ? c1 : acc[mf][nf2][half * 2 + 1] + bv1;
                *(float2*)(Cout + (size_t)row * 256 + col) = make_float2(v0, v1);
            }
        }
    }
}

// ---------------------------------------------------------------------------
// Flash attention (champion: base-2 softmax)
#define AQ_STRIDE 36
#define AK_STRIDE 36
#define AV_STRIDE 40
#define AP_STRIDE 68
#define ATTN_SMEM ((128*AQ_STRIDE + 2*64*AK_STRIDE + 2*64*AV_STRIDE + 8*16*AP_STRIDE) * 4)

__global__ void __launch_bounds__(256, 2)
attn_tc(const float* __restrict__ q, const float* __restrict__ k,
        const float* __restrict__ v, const float* __restrict__ bias,
        float* __restrict__ out) {
    extern __shared__ float sm[];
    unsigned* Qs = (unsigned*)sm;
    float*    Ks = sm + 128 * AQ_STRIDE;
    float*    Vs = Ks + 2 * 64 * AK_STRIDE;
    unsigned* Ps = (unsigned*)(Vs + 2 * 64 * AV_STRIDE);

    int b = blockIdx.x >> 3, h = blockIdx.x & 7;
    int q0 = blockIdx.y * 128;
    int tid = threadIdx.x, w = tid >> 5, lane = tid & 31;
    int g = lane >> 2, t = lane & 3;

    const float scale = 0.17677669529663687f * LOG2E;
    const float* kb_ = k + (size_t)b * Tt * Dd + h * 32;
    const float* vb_ = v + (size_t)b * Tt * Dd + h * 32;
    const float* biasb = bias + (size_t)b * Tt * Tt;

    auto issueKV = [&](int jt, int buf) {
        int j0 = jt * 64;
        float* Kb = Ks + buf * 64 * AK_STRIDE;
        float* Vb = Vs + buf * 64 * AV_STRIDE;
        #pragma unroll
        for (int r = 0; r < 2; r++) {
            int idx = tid + 256 * r;
            int key = idx >> 3, ch = idx & 7;
            int gj = j0 + key;
            bool p = gj < Tt;
            size_t off = (size_t)(p ? gj : 0) * 256 + ch * 4;
            cpa16(Kb + key * AK_STRIDE + ch * 4, kb_ + off, p);
            cpa16(Vb + key * AV_STRIDE + ch * 4, vb_ + off, p);
        }
        CP_COMMIT();
    };

    issueKV(0, 0);
    #pragma unroll
    for (int r = 0; r < 4; r++) {
        int idx = tid + 256 * r;
        int m = idx >> 3, k4 = (idx & 7) << 2;
        float4 qv = make_float4(0.f, 0.f, 0.f, 0.f);
        int qr = q0 + m;
        if (qr < Tt) qv = *(const float4*)(q + ((size_t)(b * Tt + qr)) * 256 + h * 32 + k4);
        Qs[m * AQ_STRIDE + k4 + 0] = f2tf(qv.x * scale);
        Qs[m * AQ_STRIDE + k4 + 1] = f2tf(qv.y * scale);
        Qs[m * AQ_STRIDE + k4 + 2] = f2tf(qv.z * scale);
        Qs[m * AQ_STRIDE + k4 + 3] = f2tf(qv.w * scale);
    }
    __syncthreads();
    int mb = w * 16;
    int r0g = q0 + mb + g, r1g = r0g + 8;
    bool act = (q0 + mb) < Tt;
    bool rowsok = r1g < Tt;

    unsigned qa[4][4];
    if (act) {
        #pragma unroll
        for (int ks = 0; ks < 4; ks++) {
            int kb2 = ks * 8;
            qa[ks][0] = Qs[(mb + g)     * AQ_STRIDE + kb2 + t];
            qa[ks][1] = Qs[(mb + g + 8) * AQ_STRIDE + kb2 + t];
            qa[ks][2] = Qs[(mb + g)     * AQ_STRIDE + kb2 + t + 4];
            qa[ks][3] = Qs[(mb + g + 8) * AQ_STRIDE + kb2 + t + 4];
        }
    }

    float mrow[2] = {-1e30f, -1e30f}, lrow[2] = {0.f, 0.f};
    float oacc[4][4];
    #pragma unroll
    for (int i = 0; i < 4; i++)
        #pragma unroll
        for (int c = 0; c < 4; c++) oacc[i][c] = 0.f;

    const int NTILES = (Tt + 63) / 64;  // 13

    for (int jt = 0; jt < NTILES; jt++) {
        int buf = jt & 1;
        int j0 = jt * 64;

        float s[8][4];
        if (act) {
            const float* br0 = biasb + (size_t)r0g * Tt + j0;
            const float* br1 = biasb + (size_t)r1g * Tt + j0;
            if (rowsok && jt < NTILES - 1) {
                #pragma unroll
                for (int nf = 0; nf < 8; nf++) {
                    int col = nf * 8 + 2 * t;
                    s[nf][0] = __ldg(br0 + col);
                    s[nf][1] = __ldg(br0 + col + 1);
                    s[nf][2] = __ldg(br1 + col);
                    s[nf][3] = __ldg(br1 + col + 1);
                }
            } else {
                #pragma unroll
                for (int nf = 0; nf < 8; nf++) {
                    int col = j0 + nf * 8 + 2 * t;
                    bool cok0 = col < Tt, cok1 = (col + 1) < Tt;
                    s[nf][0] = (r0g < Tt && cok0) ? __ldg(biasb + (size_t)r0g * Tt + col)     : -1e30f;
                    s[nf][1] = (r0g < Tt && cok1) ? __ldg(biasb + (size_t)r0g * Tt + col + 1) : -1e30f;
                    s[nf][2] = (rowsok && cok0)   ? __ldg(biasb + (size_t)r1g * Tt + col)     : -1e30f;
                    s[nf][3] = (rowsok && cok1)   ? __ldg(biasb + (size_t)r1g * Tt + col + 1) : -1e30f;
                }
            }
        }

        if (jt + 1 < NTILES) { issueKV(jt + 1, buf ^ 1); CP_WAIT1(); }
        else                 { CP_WAIT0(); }
        __syncthreads();

        if (act) {
            const unsigned* Kb = (const unsigned*)(Ks + buf * 64 * AK_STRIDE);
            const unsigned* Vb = (const unsigned*)(Vs + buf * 64 * AV_STRIDE);

            #pragma unroll
            for (int ks = 0; ks < 4; ks++) {
                int kb2 = ks * 8;
                #pragma unroll
                for (int nf = 0; nf < 8; nf++) {
                    unsigned b0 = Kb[(nf * 8 + g) * AK_STRIDE + kb2 + t];
                    unsigned b1 = Kb[(nf * 8 + g) * AK_STRIDE + kb2 + t + 4];
                    mma_tf32(s[nf], qa[ks][0], qa[ks][1], qa[ks][2], qa[ks][3], b0, b1);
                }
            }
            float tmax[2] = {-1e30f, -1e30f};
            #pragma unroll
            for (int nf = 0; nf < 8; nf++) {
                tmax[0] = fmaxf(tmax[0], fmaxf(s[nf][0], s[nf][1]));
                tmax[1] = fmaxf(tmax[1], fmaxf(s[nf][2], s[nf][3]));
            }
            #pragma unroll
            for (int o = 1; o <= 2; o <<= 1) {
                tmax[0] = fmaxf(tmax[0], __shfl_xor_sync(0xffffffffu, tmax[0], o));
                tmax[1] = fmaxf(tmax[1], __shfl_xor_sync(0xffffffffu, tmax[1], o));
            }
            float mn0 = fmaxf(mrow[0], tmax[0]), mn1 = fmaxf(mrow[1], tmax[1]);
            float corr0 = ex2(mrow[0] - mn0), corr1 = ex2(mrow[1] - mn1);
            mrow[0] = mn0; mrow[1] = mn1;
            float sum0 = 0.f, sum1 = 0.f;
            #pragma unroll
            for (int nf = 0; nf < 8; nf++) {
                s[nf][0] = ex2(s[nf][0] - mn0); sum0 += s[nf][0];
                s[nf][1] = ex2(s[nf][1] - mn0); sum0 += s[nf][1];
                s[nf][2] = ex2(s[nf][2] - mn1); sum1 += s[nf][2];
                s[nf][3] = ex2(s[nf][3] - mn1); sum1 += s[nf][3];
            }
            #pragma unroll
            for (int o = 1; o <= 2; o <<= 1) {
                sum0 += __shfl_xor_sync(0xffffffffu, sum0, o);
                sum1 += __shfl_xor_sync(0xffffffffu, sum1, o);
            }
            lrow[0] = lrow[0] * corr0 + sum0;
            lrow[1] = lrow[1] * corr1 + sum1;
            #pragma unroll
            for (int i = 0; i < 4; i++) {
                oacc[i][0] *= corr0; oacc[i][1] *= corr0;
                oacc[i][2] *= corr1; oacc[i][3] *= corr1;
            }
            unsigned* Pw = Ps + w * 16 * AP_STRIDE;
            #pragma unroll
            for (int nf = 0; nf < 8; nf++) {
                int col = nf * 8 + 2 * t;
                Pw[g * AP_STRIDE + col]           = f2tf(s[nf][0]);
                Pw[g * AP_STRIDE + col + 1]       = f2tf(s[nf][1]);
                Pw[(g + 8) * AP_STRIDE + col]     = f2tf(s[nf][2]);
                Pw[(g + 8) * AP_STRIDE + col + 1] = f2tf(s[nf][3]);
            }
            __syncwarp();
            #pragma unroll
            for (int ks2 = 0; ks2 < 8; ks2++) {
                int kk = ks2 * 8;
                unsigned a0 = Pw[g * AP_STRIDE + kk + t];
                unsigned a1 = Pw[(g + 8) * AP_STRIDE + kk + t];
                unsigned a2 = Pw[g * AP_STRIDE + kk + t + 4];
                unsigned a3 = Pw[(g + 8) * AP_STRIDE + kk + t + 4];
                #pragma unroll
                for (int nf2 = 0; nf2 < 4; nf2++) {
                    unsigned b0 = Vb[(kk + t)     * AV_STRIDE + nf2 * 8 + g];
                    unsigned b1 = Vb[(kk + t + 4) * AV_STRIDE + nf2 * 8 + g];
                    mma_tf32(oacc[nf2], a0, a1, a2, a3, b0, b1);
                }
            }
        }
        __syncthreads();
    }
    if (act) {
        float inv0 = 1.f / lrow[0], inv1 = 1.f / lrow[1];
        #pragma unroll
        for (int nf2 = 0; nf2 < 4; nf2++) {
            int feat = nf2 * 8 + 2 * t;
            if (r0g < Tt)
                *(float2*)(out + ((size_t)(b * Tt + r0g)) * 256 + h * 32 + feat) =
                    make_float2(roundtf(oacc[nf2][0] * inv0), roundtf(oacc[nf2][1] * inv0));
            if (rowsok)
                *(float2*)(out + ((size_t)(b * Tt + r1g)) * 256 + h * 32 + feat) =
                    make_float2(roundtf(oacc[nf2][2] * inv1), roundtf(oacc[nf2][3] * inv1));
        }
    }
}

// ---------------------------------------------------------------------------
extern "C" void kernel_launch(void* const* d_in, const int* in_sizes, int n_in,
                              void* d_out, int out_size) {
    const float* nf       = (const float*)d_in[0];
    const int*   adj      = (const int*)  d_in[1];
    const float* dist     = (const float*)d_in[2];
    const float* eoh      = (const float*)d_in[3];
    const float* npw      = (const float*)d_in[4];
    const float* npb      = (const float*)d_in[5];
    const float* cls      = (const float*)d_in[6];
    const float* etw      = (const float*)d_in[7];
    const float* noedge   = (const float*)d_in[8];
    const float* degscale = (const float*)d_in[9];
    const float* gamma    = (const float*)d_in[10];
    const float* v2n      = (const float*)d_in[11];
    const float* n2v      = (const float*)d_in[12];
    const float* vself    = (const float*)d_in[13];
    const float* ln1g = (const float*)d_in[14]; const float* ln1b = (const float*)d_in[15];
    const float* qw   = (const float*)d_in[16]; const float* qb   = (const float*)d_in[17];
    const float* kw   = (const float*)d_in[18]; const float* kb   = (const float*)d_in[19];
    const float* vw   = (const float*)d_in[20]; const float* vb   = (const float*)d_in[21];
    const float* ow   = (const float*)d_in[22]; const float* ob   = (const float*)d_in[23];
    const float* ln2g = (const float*)d_in[24]; const float* ln2b = (const float*)d_in[25];
    const float* fc1w = (const float*)d_in[26]; const float* fc1b = (const float*)d_in[27];
    const float* fc2w = (const float*)d_in[28]; const float* fc2b = (const float*)d_in[29];

    float *p_x, *p_xn, *p_q, *p_k, *p_v, *p_att, *p_m1, *p_bias, *p_wr, *p_npwr;
    cudaGetSymbolAddress((void**)&p_x,    g_x);
    cudaGetSymbolAddress((void**)&p_xn,   g_xn);
    cudaGetSymbolAddress((void**)&p_q,    g_q);
    cudaGetSymbolAddress((void**)&p_k,    g_k);
    cudaGetSymbolAddress((void**)&p_v,    g_v);
    cudaGetSymbolAddress((void**)&p_att,  g_att);
    cudaGetSymbolAddress((void**)&p_m1,   g_m1);
    cudaGetSymbolAddress((void**)&p_bias, g_bias);
    cudaGetSymbolAddress((void**)&p_wr,   g_wr);
    cudaGetSymbolAddress((void**)&p_npwr, g_npwr);

    cudaFuncSetAttribute(gemm_qkv,    cudaFuncAttributeMaxDynamicSharedMemorySize, GEMM_SMEM);
    cudaFuncSetAttribute(gemm_one<1>, cudaFuncAttributeMaxDynamicSharedMemorySize, GEMM_SMEM);
    cudaFuncSetAttribute(gemm_one<2>, cudaFuncAttributeMaxDynamicSharedMemorySize, GEMM_SMEM);
    cudaFuncSetAttribute(proj_gemm,   cudaFuncAttributeMaxDynamicSharedMemorySize, GEMM_SMEM);
    cudaFuncSetAttribute(attn_tc,     cudaFuncAttributeMaxDynamicSharedMemorySize, ATTN_SMEM);

    roundw_kernel<<<6 * LDD / 256, 256>>>(qw, kw, vw, ow, fc1w, fc2w);
    roundnpw_kernel<<<Ff * Dd / 256, 256>>>(npw);
    deg_kernel<<<(Bq * Nn) / 8, 256>>>(adj);
    bias_edge_kernel<<<dim3(Nn, Bq), 256>>>(adj, dist, eoh, etw, noedge, degscale, gamma,
                                            v2n, n2v, vself);

    proj_gemm<<<dim3(2, (Mrows + 127) / 128), 256, GEMM_SMEM>>>(nf, p_npwr, npb, cls, p_x);

    dim3 ggrid (2, (Mrows + 127) / 128);    // (2, 49)
    dim3 qgrid (6, (Mrows + 127) / 128);    // (6, 49)
    dim3 agrid (Bq * Hh, (Tt + 127) / 128); // (64, 7)
    for (int l = 0; l < Ll; l++) {
        size_t wo = (size_t)l * Dd * Dd;
        size_t bo = (size_t)l * Dd;
        bool last = (l == Ll - 1);
        ln_kernel<<<Mrows / 8, 256>>>(p_x, ln1g + bo, ln1b + bo, p_xn);
        gemm_qkv<<<qgrid, 256, GEMM_SMEM>>>(p_xn, p_wr + wo,
                                            qb + bo, p_q, kb + bo, p_k, vb + bo, p_v);
        attn_tc<<<agrid, 256, ATTN_SMEM>>>(p_q, p_k, p_v, p_bias, p_att);
        gemm_one<2><<<ggrid, 256, GEMM_SMEM>>>(p_att, p_wr + 3 * LDD + wo, ob + bo, p_x, p_x);
        ln_kernel<<<Mrows / 8, 256>>>(p_x, ln2g + bo, ln2b + bo, p_xn);
        gemm_one<1><<<ggrid, 256, GEMM_SMEM>>>(p_xn, p_wr + 4 * LDD + wo, fc1b + bo, p_m1, p_m1);
        gemm_one<2><<<ggrid, 256, GEMM_SMEM>>>(p_m1, p_wr + 5 * LDD + wo, fc2b + bo,
                                               p_x, last ? (float*)d_out : p_x);
    }
}